// round 11
// baseline (speedup 1.0000x reference)
#include <cuda_runtime.h>
#include <cuda_bf16.h>
#include <math.h>
#include <stdint.h>

// ---------------------------------------------------------------------------
#define D_MODEL   256
#define DEPTH     2
#define D_INNER   512
#define D_STATE   16
#define D_CONV    4
#define DT_RANK   16
#define BATCH     2
#define SEQLEN    2048
#define NTOK      (BATCH * SEQLEN)          // 4096
#define DBL_COLS  (DT_RANK + 2 * D_STATE)   // 48

#define NCHUNK    32
#define CLEN      (SEQLEN / NCHUNK)         // 64
#define XP_SK     8
#define NFLAGS    (BATCH * NCHUNK * 32)     // 2048

// ---------------------------------------------------------------------------
// Scratch
// ---------------------------------------------------------------------------
__device__ float    g_h    [NTOK * D_MODEL];
__device__ float    g_xz   [NTOK * 2 * D_INNER];
__device__ float    g_xc   [NTOK * D_INNER];
__device__ float    g_dbl  [NTOK * DBL_COLS];
__device__ float    g_part [XP_SK * NTOK * DBL_COLS];
__device__ float    g_y    [NTOK * D_INNER];
__device__ float    g_cA   [BATCH * NCHUNK * D_INNER * D_STATE];
__device__ float    g_cH   [BATCH * NCHUNK * D_INNER * D_STATE];
__device__ int      g_flag [NFLAGS];
__device__ unsigned g_bar;

// ---------------------------------------------------------------------------
// cp.async helpers
// ---------------------------------------------------------------------------
__device__ __forceinline__ uint32_t smem_u32(const void* p) {
    uint32_t a;
    asm("{.reg .u64 t; cvta.to.shared.u64 t, %1; cvt.u32.u64 %0, t;}"
        : "=r"(a) : "l"(p));
    return a;
}
__device__ __forceinline__ void cp_async16(void* dst, const void* src) {
    asm volatile("cp.async.ca.shared.global [%0], [%1], 16;"
                 :: "r"(smem_u32(dst)), "l"(src));
}
__device__ __forceinline__ void cp_async16_z(void* dst, const void* src, bool ok) {
    int sz = ok ? 16 : 0;
    asm volatile("cp.async.ca.shared.global [%0], [%1], 16, %2;"
                 :: "r"(smem_u32(dst)), "l"(src), "r"(sz));
}
#define CP_COMMIT() asm volatile("cp.async.commit_group;")
#define CP_WAIT1()  asm volatile("cp.async.wait_group 1;")
#define CP_WAIT0()  asm volatile("cp.async.wait_group 0;")

// ---------------------------------------------------------------------------
// Grid-wide barrier (all CTAs resident by construction).
// ---------------------------------------------------------------------------
__device__ __forceinline__ void grid_bar(unsigned phase) {
    __syncthreads();
    if (threadIdx.x == 0) {
        __threadfence();
        atomicAdd(&g_bar, 1u);
        unsigned target = gridDim.x * phase;
        unsigned v;
        do {
            asm volatile("ld.acquire.gpu.u32 %0, [%1];" : "=r"(v) : "l"(&g_bar) : "memory");
        } while (v < target);
    }
    __syncthreads();
}

// ---------------------------------------------------------------------------
// GEMM tile (BM=128, BN=64, BK=16, 3-stage cp.async; MODE 0 store / 2 += )
// smem: As = 3*128*20 u32 (30720B), Bs = 3*64*20 u32 (15360B)
// ---------------------------------------------------------------------------
template <int MODE>
__device__ __forceinline__ void gemm_tile(uint32_t* As, uint32_t* Bs,
    const float* __restrict__ A, int lda,
    const float* __restrict__ W, int ldw,
    float* __restrict__ C, int ldc,
    int N, int K, int m0, int n0)
{
    const int BM = 128, BN = 64, BK = 16, LDS = 20, S = 3;
    int tid  = threadIdx.x;
    int lane = tid & 31;
    int warp = tid >> 5;
    int wm = (warp >> 1) * 32;
    int wn = (warp & 1) * 32;
    int gr = lane >> 2;
    int gc = lane & 3;

    float acc[2][4][4];
    #pragma unroll
    for (int mi = 0; mi < 2; mi++)
        #pragma unroll
        for (int ni = 0; ni < 4; ni++)
            #pragma unroll
            for (int e = 0; e < 4; e++) acc[mi][ni][e] = 0.f;

    int lrow = tid >> 2;
    int lcol = (tid & 3) * 4;

    auto issue = [&](int ti) {
        int buf = ti % S;
        int k0  = ti * BK;
        #pragma unroll
        for (int h = 0; h < 2; h++) {
            int r = lrow + h * 64;
            cp_async16(&As[buf * BM * LDS + r * LDS + lcol],
                       &A[(size_t)(m0 + r) * lda + k0 + lcol]);
        }
        {
            int r = lrow;
            bool ok = (n0 + r) < N;
            const float* src = ok ? &W[(size_t)(n0 + r) * ldw + k0 + lcol] : W;
            cp_async16_z(&Bs[buf * BN * LDS + r * LDS + lcol], src, ok);
        }
        CP_COMMIT();
    };

    int nk = K / BK;
    issue(0);
    if (nk > 1) issue(1);

    for (int i = 0; i < nk; i++) {
        if (i + 1 < nk) { CP_WAIT1(); } else { CP_WAIT0(); }   // race fix
        __syncthreads();
        if (i + 2 < nk) issue(i + 2);
        int buf = i % S;
        const uint32_t* Ab = &As[buf * BM * LDS];
        const uint32_t* Bb = &Bs[buf * BN * LDS];

        #pragma unroll
        for (int ks = 0; ks < BK; ks += 8) {
            uint32_t a[2][4], b[4][2];
            #pragma unroll
            for (int mi = 0; mi < 2; mi++) {
                int rb = wm + mi * 16 + gr;
                a[mi][0] = Ab[rb * LDS + ks + gc];
                a[mi][1] = Ab[(rb + 8) * LDS + ks + gc];
                a[mi][2] = Ab[rb * LDS + ks + gc + 4];
                a[mi][3] = Ab[(rb + 8) * LDS + ks + gc + 4];
            }
            #pragma unroll
            for (int ni = 0; ni < 4; ni++) {
                int rb = wn + ni * 8 + gr;
                b[ni][0] = Bb[rb * LDS + ks + gc];
                b[ni][1] = Bb[rb * LDS + ks + gc + 4];
            }
            #pragma unroll
            for (int mi = 0; mi < 2; mi++)
                #pragma unroll
                for (int ni = 0; ni < 4; ni++)
                    asm volatile(
                        "mma.sync.aligned.m16n8k8.row.col.f32.tf32.tf32.f32 "
                        "{%0,%1,%2,%3}, {%4,%5,%6,%7}, {%8,%9}, {%0,%1,%2,%3};"
                        : "+f"(acc[mi][ni][0]), "+f"(acc[mi][ni][1]),
                          "+f"(acc[mi][ni][2]), "+f"(acc[mi][ni][3])
                        : "r"(a[mi][0]), "r"(a[mi][1]), "r"(a[mi][2]), "r"(a[mi][3]),
                          "r"(b[ni][0]), "r"(b[ni][1]));
        }
    }
    __syncthreads();   // protect smem against next tile's issue(0/1)

    #pragma unroll
    for (int mi = 0; mi < 2; mi++) {
        #pragma unroll
        for (int ni = 0; ni < 4; ni++) {
            int col = n0 + wn + ni * 8 + gc * 2;
            if (col < N) {
                #pragma unroll
                for (int half = 0; half < 2; half++) {
                    int row = m0 + wm + mi * 16 + gr + half * 8;
                    float2 v = make_float2(acc[mi][ni][half * 2],
                                           acc[mi][ni][half * 2 + 1]);
                    float2* cp = (float2*)&C[(size_t)row * ldc + col];
                    if (MODE == 2) {
                        float2 o = *cp;
                        v.x += o.x; v.y += o.y;
                    }
                    *cp = v;
                }
            }
        }
    }
}

// ---------------------------------------------------------------------------
// Scan item (one (b, chunk, dg)); smem carved from shared pool.
// ---------------------------------------------------------------------------
__device__ __forceinline__ void scan_item(int item, char* sm,
    const float* __restrict__ dbl, const float* __restrict__ xc,
    const float* __restrict__ xz, const float* __restrict__ A_log,
    const float* __restrict__ dpw, const float* __restrict__ dpb,
    const float* __restrict__ Dp, float* __restrict__ cA,
    float* __restrict__ cH, int* __restrict__ flags, float* __restrict__ y)
{
    float* s_dt = (float*)sm;                       // 64*16
    float* s_B  = s_dt + CLEN * 16;
    float* s_C  = s_B  + CLEN * 16;
    float* s_xc = s_C  + CLEN * 16;
    float* s_dl = s_xc + CLEN * 16;
    float* s_pw = s_dl + CLEN * 16;                 // 16*17
    float* s_y  = s_dt;

    int dg = item & 31;
    int c  = (item >> 5) & (NCHUNK - 1);
    int b  = item >> 10;
    int tid = threadIdx.x;
    int n  = tid & 15;
    int dl = tid >> 4;
    int d  = dg * 16 + dl;
    int l0 = c * CLEN;

    const float4* dbl4 = (const float4*)(dbl + ((size_t)b * SEQLEN + l0) * DBL_COLS);
    const float*  xc_p = xc + ((size_t)b * SEQLEN + l0) * D_INNER + dg * 16;

    for (int idx = tid; idx < CLEN * 12; idx += 256) {
        int l = idx / 12, g = idx % 12;
        float4 v = dbl4[l * 12 + g];
        int cc = g * 4;
        float* dst = (cc < 16) ? &s_dt[l * 16 + cc]
                   : (cc < 32) ? &s_B [l * 16 + cc - 16]
                               : &s_C [l * 16 + cc - 32];
        *(float4*)dst = v;
    }
    {
        int l = tid >> 2, g = tid & 3;
        *(float4*)&s_xc[l * 16 + g * 4] =
            *(const float4*)&xc_p[(size_t)l * D_INNER + g * 4];
    }
    {
        int rr = tid >> 4, cc = tid & 15;
        s_pw[rr * 17 + cc] = dpw[(size_t)(dg * 16 + rr) * DT_RANK + cc];
    }
    __syncthreads();

    for (int idx = tid; idx < CLEN * 16; idx += 256) {
        int l = idx >> 4, dd = idx & 15;
        float acc = dpb[dg * 16 + dd];
        #pragma unroll
        for (int r = 0; r < 16; r++)
            acc += s_dt[l * 16 + r] * s_pw[dd * 17 + r];
        s_dl[l * 16 + dd] = (acc > 20.f) ? acc : log1pf(__expf(acc));
    }
    __syncthreads();

    float Adn = -__expf(A_log[d * D_STATE + n]);

    float hloc = 0.f, P = 1.f;
    #pragma unroll 8
    for (int l = 0; l < CLEN; l++) {
        float dv = s_dl[l * 16 + dl];
        float a  = __expf(dv * Adn);
        hloc = a * hloc + (dv * s_xc[l * 16 + dl]) * s_B[l * 16 + n];
        P *= a;
    }

    size_t col_base = (((size_t)b * NCHUNK) * D_INNER + d) * D_STATE + n;
    size_t cstride  = (size_t)D_INNER * D_STATE;
    cA[col_base + (size_t)c * cstride] = P;
    cH[col_base + (size_t)c * cstride] = hloc;
    __threadfence();
    __syncthreads();
    if (tid == 0) {
        int* fp = &flags[(b * NCHUNK + c) * 32 + dg];
        asm volatile("st.release.gpu.b32 [%0], %1;" :: "l"(fp), "r"(1) : "memory");
    }

    float h = 0.f;
    if (c > 0) {
        if (tid < c) {
            const int* fp = &flags[(b * NCHUNK + tid) * 32 + dg];
            int v;
            do {
                asm volatile("ld.acquire.gpu.b32 %0, [%1];" : "=r"(v) : "l"(fp) : "memory");
            } while (v == 0);
        }
        __syncthreads();
        for (int j = 0; j < c; j++) {
            size_t o = col_base + (size_t)j * cstride;
            h = cA[o] * h + cH[o];
        }
    }

    #pragma unroll 4
    for (int l = 0; l < CLEN; l++) {
        float dv = s_dl[l * 16 + dl];
        h = __expf(dv * Adn) * h + (dv * s_xc[l * 16 + dl]) * s_B[l * 16 + n];
        float p = h * s_C[l * 16 + n];
        p += __shfl_xor_sync(0xffffffffu, p, 8);
        p += __shfl_xor_sync(0xffffffffu, p, 4);
        p += __shfl_xor_sync(0xffffffffu, p, 2);
        p += __shfl_xor_sync(0xffffffffu, p, 1);
        if (n == 0) s_y[l * 16 + dl] = p;
    }
    __syncthreads();

    const float* z_p = xz + ((size_t)b * SEQLEN + l0) * 2 * D_INNER + D_INNER + dg * 16;
    float*       y_p = y  + ((size_t)b * SEQLEN + l0) * D_INNER + dg * 16;
    const float4 Dv = ((const float4*)Dp)[dg * 4 + (tid & 3)];
    {
        int l = tid >> 2, g = tid & 3;
        float4 z4 = *(const float4*)&z_p[(size_t)l * 2 * D_INNER + g * 4];
        float4 yv = *(float4*)&s_y[l * 16 + g * 4];
        float4 xv = *(float4*)&s_xc[l * 16 + g * 4];
        float4 o;
        o.x = (yv.x + xv.x * Dv.x) * (z4.x / (1.f + __expf(-z4.x)));
        o.y = (yv.y + xv.y * Dv.y) * (z4.y / (1.f + __expf(-z4.y)));
        o.z = (yv.z + xv.z * Dv.z) * (z4.z / (1.f + __expf(-z4.z)));
        o.w = (yv.w + xv.w * Dv.w) * (z4.w / (1.f + __expf(-z4.w)));
        *(float4*)&y_p[(size_t)l * D_INNER + g * 4] = o;
    }
    __syncthreads();   // smem reuse by next item
}

// ---------------------------------------------------------------------------
// The persistent megakernel
// ---------------------------------------------------------------------------
__global__ __launch_bounds__(256)
void mega(float* __restrict__ xbuf,
          const float* __restrict__ ln_w, const float* __restrict__ ln_b,
          const float* __restrict__ ipw,  const float* __restrict__ cw,
          const float* __restrict__ cb,   const float* __restrict__ xpw,
          const float* __restrict__ dpw,  const float* __restrict__ dpb,
          const float* __restrict__ alog, const float* __restrict__ dpar,
          const float* __restrict__ opw)
{
    __shared__ __align__(16) char SM[46080];   // union: GEMM 46080B / scan 21568B
    uint32_t* As = (uint32_t*)SM;
    uint32_t* Bs = (uint32_t*)(SM + 3 * 128 * 20 * 4);

    int tid  = threadIdx.x;
    int lane = tid & 31;
    int warp = tid >> 5;
    unsigned phase = 0;

    for (int layer = 0; layer < DEPTH; layer++) {
        const float* l_lnw  = ln_w + layer * D_MODEL;
        const float* l_lnb  = ln_b + layer * D_MODEL;
        const float* l_ipw  = ipw  + (size_t)layer * 2 * D_INNER * D_MODEL;
        const float* l_cw   = cw   + (size_t)layer * D_INNER * D_CONV;
        const float* l_cb   = cb   + (size_t)layer * D_INNER;
        const float* l_xpw  = xpw  + (size_t)layer * DBL_COLS * D_INNER;
        const float* l_dpw  = dpw  + (size_t)layer * D_INNER * DT_RANK;
        const float* l_dpb  = dpb  + (size_t)layer * D_INNER;
        const float* l_alog = alog + (size_t)layer * D_INNER * D_STATE;
        const float* l_dpar = dpar + (size_t)layer * D_INNER;
        const float* l_opw  = opw  + (size_t)layer * D_MODEL * D_INNER;

        // ---- 1. LayerNorm (warp per token) ----
        {
            const float4* x4  = (const float4*)xbuf;
            float4*       h4  = (float4*)g_h;
            const float4* w4  = (const float4*)l_lnw;
            const float4* b4  = (const float4*)l_lnb;
            for (int t = blockIdx.x * 8 + warp; t < NTOK; t += gridDim.x * 8) {
                float4 a = x4[(size_t)t * 64 + lane];
                float4 bb = x4[(size_t)t * 64 + 32 + lane];
                float s = a.x + a.y + a.z + a.w + bb.x + bb.y + bb.z + bb.w;
                float q = a.x * a.x + a.y * a.y + a.z * a.z + a.w * a.w
                        + bb.x * bb.x + bb.y * bb.y + bb.z * bb.z + bb.w * bb.w;
                #pragma unroll
                for (int o = 16; o > 0; o >>= 1) {
                    s += __shfl_xor_sync(0xffffffffu, s, o);
                    q += __shfl_xor_sync(0xffffffffu, q, o);
                }
                float mu  = s * (1.f / D_MODEL);
                float var = q * (1.f / D_MODEL) - mu * mu;
                float inv = rsqrtf(var + 1e-5f);
                float4 w1 = w4[lane], w2 = w4[32 + lane];
                float4 b1 = b4[lane], b2 = b4[32 + lane];
                float4 o1, o2;
                o1.x = (a.x - mu) * inv * w1.x + b1.x;
                o1.y = (a.y - mu) * inv * w1.y + b1.y;
                o1.z = (a.z - mu) * inv * w1.z + b1.z;
                o1.w = (a.w - mu) * inv * w1.w + b1.w;
                o2.x = (bb.x - mu) * inv * w2.x + b2.x;
                o2.y = (bb.y - mu) * inv * w2.y + b2.y;
                o2.z = (bb.z - mu) * inv * w2.z + b2.z;
                o2.w = (bb.w - mu) * inv * w2.w + b2.w;
                h4[(size_t)t * 64 + lane]      = o1;
                h4[(size_t)t * 64 + 32 + lane] = o2;
            }
        }
        grid_bar(++phase);

        // ---- 2. in_proj: 512 tiles of 128x64 ----
        for (int t = blockIdx.x; t < 16 * 32; t += gridDim.x) {
            int n0 = (t & 15) * 64, m0 = (t >> 4) * 128;
            gemm_tile<0>(As, Bs, g_h, D_MODEL, l_ipw, D_MODEL,
                         g_xz, 2 * D_INNER, 2 * D_INNER, D_MODEL, m0, n0);
        }
        grid_bar(++phase);

        // ---- 3. conv + silu (float4 grid-stride) ----
        {
            const int DV = D_INNER / 4;
            for (int idx = blockIdx.x * 256 + tid; idx < NTOK * DV;
                 idx += gridDim.x * 256) {
                int d4 = idx & (DV - 1);
                int t  = idx >> 7;
                int l  = t & (SEQLEN - 1);
                int d  = d4 * 4;
                const float4* row = (const float4*)g_xz + (size_t)t * (2 * D_INNER / 4) + d4;
                const int RS = 2 * D_INNER / 4;
                float4 z4 = make_float4(0.f, 0.f, 0.f, 0.f);
                float4 r0 = (l >= 3) ? row[-3 * RS] : z4;
                float4 r1 = (l >= 2) ? row[-2 * RS] : z4;
                float4 r2 = (l >= 1) ? row[-1 * RS] : z4;
                float4 r3 = row[0];
                const float4* cw4 = (const float4*)l_cw;
                float4 w0 = cw4[d + 0], w1 = cw4[d + 1], w2 = cw4[d + 2], w3 = cw4[d + 3];
                float4 bb = ((const float4*)l_cb)[d4];
                float4 o;
                o.x = bb.x + r0.x * w0.x + r1.x * w0.y + r2.x * w0.z + r3.x * w0.w;
                o.y = bb.y + r0.y * w1.x + r1.y * w1.y + r2.y * w1.z + r3.y * w1.w;
                o.z = bb.z + r0.z * w2.x + r1.z * w2.y + r2.z * w2.z + r3.z * w2.w;
                o.w = bb.w + r0.w * w3.x + r1.w * w3.y + r2.w * w3.z + r3.w * w3.w;
                o.x = o.x / (1.f + __expf(-o.x));
                o.y = o.y / (1.f + __expf(-o.y));
                o.z = o.z / (1.f + __expf(-o.z));
                o.w = o.w / (1.f + __expf(-o.w));
                ((float4*)g_xc)[idx] = o;
            }
        }
        grid_bar(++phase);

        // ---- 4. x_proj split-K=8: 256 tiles ----
        for (int t = blockIdx.x; t < 32 * XP_SK; t += gridDim.x) {
            int m0 = (t & 31) * 128, z = t >> 5;
            gemm_tile<0>(As, Bs,
                         g_xc + z * (D_INNER / XP_SK), D_INNER,
                         l_xpw + z * (D_INNER / XP_SK), D_INNER,
                         g_part + (size_t)z * NTOK * DBL_COLS, DBL_COLS,
                         DBL_COLS, D_INNER / XP_SK, m0, 0);
        }
        grid_bar(++phase);

        // ---- 5. reduce partials + zero flags ----
        {
            const int NV = NTOK * DBL_COLS / 4;
            for (int i = blockIdx.x * 256 + tid; i < NV; i += gridDim.x * 256) {
                float4 s = ((const float4*)g_part)[i];
                #pragma unroll
                for (int z = 1; z < XP_SK; z++) {
                    float4 p = ((const float4*)g_part)[(size_t)z * NV + i];
                    s.x += p.x; s.y += p.y; s.z += p.z; s.w += p.w;
                }
                ((float4*)g_dbl)[i] = s;
            }
            for (int i = blockIdx.x * 256 + tid; i < NFLAGS; i += gridDim.x * 256)
                g_flag[i] = 0;
        }
        grid_bar(++phase);

        // ---- 6. fused scan (lookback across resident CTAs) ----
        for (int it = blockIdx.x; it < NFLAGS; it += gridDim.x)
            scan_item(it, SM, g_dbl, g_xc, g_xz, l_alog, l_dpw, l_dpb,
                      l_dpar, g_cA, g_cH, g_flag, g_y);
        grid_bar(++phase);

        // ---- 7. out_proj + residual: 128 tiles ----
        for (int t = blockIdx.x; t < 4 * 32; t += gridDim.x) {
            int n0 = (t & 3) * 64, m0 = (t >> 2) * 128;
            gemm_tile<2>(As, Bs, g_y, D_INNER, l_opw, D_INNER,
                         xbuf, D_MODEL, D_MODEL, D_INNER, m0, n0);
        }
        grid_bar(++phase);
    }
}

// ---------------------------------------------------------------------------
// Launcher
// ---------------------------------------------------------------------------
extern "C" void kernel_launch(void* const* d_in, const int* in_sizes, int n_in,
                              void* d_out, int out_size)
{
    const float* x_in = (const float*)d_in[0];
    const float* ln_w = (const float*)d_in[1];
    const float* ln_b = (const float*)d_in[2];
    const float* ipw  = (const float*)d_in[3];
    const float* cw   = (const float*)d_in[4];
    const float* cb   = (const float*)d_in[5];
    const float* xpw  = (const float*)d_in[6];
    const float* dpw  = (const float*)d_in[7];
    const float* dpb  = (const float*)d_in[8];
    const float* alog = (const float*)d_in[9];
    const float* dpar = (const float*)d_in[10];
    const float* opw  = (const float*)d_in[11];
    float* xbuf = (float*)d_out;

    // residual stream = d_out, initialized from input
    cudaMemcpyAsync(xbuf, x_in, (size_t)NTOK * D_MODEL * sizeof(float),
                    cudaMemcpyDeviceToDevice);

    // reset the grid barrier counter (graph-capturable memset)
    void* p_bar = nullptr;
    cudaGetSymbolAddress(&p_bar, g_bar);
    cudaMemsetAsync(p_bar, 0, sizeof(unsigned));

    // residency-safe grid size
    int nb = 1;
    cudaOccupancyMaxActiveBlocksPerMultiprocessor(&nb, mega, 256, 0);
    if (nb < 1) nb = 1;
    if (nb > 4) nb = 4;
    int nsm = 148;
    cudaDeviceGetAttribute(&nsm, cudaDevAttrMultiProcessorCount, 0);
    int ncta = nb * nsm;

    mega<<<ncta, 256>>>(xbuf, ln_w, ln_b, ipw, cw, cb, xpw,
                        dpw, dpb, alog, dpar, opw);
}

// round 12
// speedup vs baseline: 1.3169x; 1.3169x over previous
#include <cuda_runtime.h>
#include <cuda_bf16.h>
#include <math.h>
#include <stdint.h>

// ---------------------------------------------------------------------------
#define D_MODEL   256
#define DEPTH     2
#define D_INNER   512
#define D_STATE   16
#define D_CONV    4
#define DT_RANK   16
#define BATCH     2
#define SEQLEN    2048
#define NTOK      (BATCH * SEQLEN)          // 4096
#define DBL_COLS  (DT_RANK + 2 * D_STATE)   // 48

#define NCHUNK    32
#define CLEN      (SEQLEN / NCHUNK)         // 64
#define XP_SK     8
#define NFLAGS    (BATCH * NCHUNK * 32)

#define GRID_WAIT() asm volatile("griddepcontrol.wait;" ::: "memory")

// ---------------------------------------------------------------------------
// Scratch
// ---------------------------------------------------------------------------
__device__ float g_h    [NTOK * D_MODEL];
__device__ float g_xz   [NTOK * 2 * D_INNER];
__device__ float g_xc   [NTOK * D_INNER];
__device__ float g_part [XP_SK * NTOK * DBL_COLS];
__device__ float g_y    [NTOK * D_INNER];
__device__ float g_cA   [BATCH * NCHUNK * D_INNER * D_STATE];
__device__ float g_cH   [BATCH * NCHUNK * D_INNER * D_STATE];
__device__ int   g_flag [NFLAGS];

// ---------------------------------------------------------------------------
// cp.async helpers
// ---------------------------------------------------------------------------
__device__ __forceinline__ uint32_t smem_u32(const void* p) {
    uint32_t a;
    asm("{.reg .u64 t; cvta.to.shared.u64 t, %1; cvt.u32.u64 %0, t;}"
        : "=r"(a) : "l"(p));
    return a;
}
__device__ __forceinline__ void cp_async16(void* dst, const void* src) {
    asm volatile("cp.async.ca.shared.global [%0], [%1], 16;"
                 :: "r"(smem_u32(dst)), "l"(src));
}
__device__ __forceinline__ void cp_async16_z(void* dst, const void* src, bool ok) {
    int sz = ok ? 16 : 0;
    asm volatile("cp.async.ca.shared.global [%0], [%1], 16, %2;"
                 :: "r"(smem_u32(dst)), "l"(src), "r"(sz));
}
#define CP_COMMIT() asm volatile("cp.async.commit_group;")
#define CP_WAIT1()  asm volatile("cp.async.wait_group 1;")
#define CP_WAIT0()  asm volatile("cp.async.wait_group 0;")

// ---------------------------------------------------------------------------
// LayerNorm: one block per token, 256 threads
// ---------------------------------------------------------------------------
__global__ void ln_kernel(const float* __restrict__ x,
                          const float* __restrict__ w,
                          const float* __restrict__ b,
                          float* __restrict__ out)
{
    GRID_WAIT();
    __shared__ float s_sum[8], s_sq[8];
    int t = blockIdx.x;
    int d = threadIdx.x;
    float v = x[t * D_MODEL + d];

    float s = v, q = v * v;
    #pragma unroll
    for (int o = 16; o > 0; o >>= 1) {
        s += __shfl_xor_sync(0xffffffffu, s, o);
        q += __shfl_xor_sync(0xffffffffu, q, o);
    }
    int warp = threadIdx.x >> 5;
    if ((threadIdx.x & 31) == 0) { s_sum[warp] = s; s_sq[warp] = q; }
    __syncthreads();
    if (threadIdx.x < 8) { s = s_sum[threadIdx.x]; q = s_sq[threadIdx.x]; }
    else                 { s = 0.f; q = 0.f; }
    if (warp == 0) {
        #pragma unroll
        for (int o = 4; o > 0; o >>= 1) {
            s += __shfl_xor_sync(0xffffffffu, s, o);
            q += __shfl_xor_sync(0xffffffffu, q, o);
        }
        if (threadIdx.x == 0) { s_sum[0] = s; s_sq[0] = q; }
    }
    __syncthreads();
    float mu  = s_sum[0] * (1.f / D_MODEL);
    float var = s_sq[0] * (1.f / D_MODEL) - mu * mu;
    float inv = rsqrtf(var + 1e-5f);
    out[t * D_MODEL + d] = (v - mu) * inv * w[d] + b[d];
}

// ---------------------------------------------------------------------------
// tf32 tensor-core GEMM, 3-stage cp.async pipeline (race-fixed).
// C[M,N] = A[M,K] @ W[N,K]^T.  MODE 0: store | MODE 2: C += acc.
// BM=64*MT, BN=16*NI. 256 threads = 8 warps (4Mx2N).
// blockIdx.z = split-K slice.
// ---------------------------------------------------------------------------
template <int MODE, int MT, int NI>
__global__ __launch_bounds__(256)
void gemm_tf32(const float* __restrict__ A, int lda,
               const float* __restrict__ W, int ldw,
               float*       __restrict__ C, int ldc,
               int N, int K, size_t csplit)
{
    GRID_WAIT();
    const int BM = 64 * MT, BN = 16 * NI, BK = 16, LDS = 20, S = 3;
    __shared__ uint32_t As[S][BM * LDS];
    __shared__ uint32_t Bs[S][BN * LDS];

    A += (size_t)blockIdx.z * K;
    C += (size_t)blockIdx.z * csplit;

    int tid  = threadIdx.x;
    int lane = tid & 31;
    int warp = tid >> 5;
    int m0 = blockIdx.y * BM;
    int n0 = blockIdx.x * BN;
    int wm = (warp >> 1) * 16 * MT;
    int wn = (warp & 1) * 8 * NI;
    int gr = lane >> 2;
    int gc = lane & 3;

    float acc[MT][NI][4];
    #pragma unroll
    for (int mi = 0; mi < MT; mi++)
        #pragma unroll
        for (int ni = 0; ni < NI; ni++)
            #pragma unroll
            for (int e = 0; e < 4; e++) acc[mi][ni][e] = 0.f;

    int lrow = tid >> 2;
    int lcol = (tid & 3) * 4;

    auto issue = [&](int ti) {
        int buf = ti % S;
        int k0  = ti * BK;
        #pragma unroll
        for (int h = 0; h < MT; h++) {
            int r = lrow + h * 64;
            cp_async16(&As[buf][r * LDS + lcol],
                       &A[(size_t)(m0 + r) * lda + k0 + lcol]);
        }
        #pragma unroll
        for (int h = 0; h < NI / 4; h++) {
            int r = lrow + h * 64;
            bool ok = (n0 + r) < N;
            const float* src = ok ? &W[(size_t)(n0 + r) * ldw + k0 + lcol] : W;
            cp_async16_z(&Bs[buf][r * LDS + lcol], src, ok);
        }
        CP_COMMIT();
    };

    int nk = K / BK;
    issue(0);
    if (nk > 1) issue(1);

    for (int i = 0; i < nk; i++) {
        if (i + 1 < nk) { CP_WAIT1(); } else { CP_WAIT0(); }
        __syncthreads();
        if (i + 2 < nk) issue(i + 2);
        int buf = i % S;

        #pragma unroll
        for (int ks = 0; ks < BK; ks += 8) {
            uint32_t a[MT][4], b[NI][2];
            #pragma unroll
            for (int mi = 0; mi < MT; mi++) {
                int rb = wm + mi * 16 + gr;
                a[mi][0] = As[buf][rb * LDS + ks + gc];
                a[mi][1] = As[buf][(rb + 8) * LDS + ks + gc];
                a[mi][2] = As[buf][rb * LDS + ks + gc + 4];
                a[mi][3] = As[buf][(rb + 8) * LDS + ks + gc + 4];
            }
            #pragma unroll
            for (int ni = 0; ni < NI; ni++) {
                int rb = wn + ni * 8 + gr;
                b[ni][0] = Bs[buf][rb * LDS + ks + gc];
                b[ni][1] = Bs[buf][rb * LDS + ks + gc + 4];
            }
            #pragma unroll
            for (int mi = 0; mi < MT; mi++)
                #pragma unroll
                for (int ni = 0; ni < NI; ni++)
                    asm volatile(
                        "mma.sync.aligned.m16n8k8.row.col.f32.tf32.tf32.f32 "
                        "{%0,%1,%2,%3}, {%4,%5,%6,%7}, {%8,%9}, {%0,%1,%2,%3};"
                        : "+f"(acc[mi][ni][0]), "+f"(acc[mi][ni][1]),
                          "+f"(acc[mi][ni][2]), "+f"(acc[mi][ni][3])
                        : "r"(a[mi][0]), "r"(a[mi][1]), "r"(a[mi][2]), "r"(a[mi][3]),
                          "r"(b[ni][0]), "r"(b[ni][1]));
        }
    }

    #pragma unroll
    for (int mi = 0; mi < MT; mi++) {
        #pragma unroll
        for (int ni = 0; ni < NI; ni++) {
            int col = n0 + wn + ni * 8 + gc * 2;
            if (col < N) {
                #pragma unroll
                for (int half = 0; half < 2; half++) {
                    int row = m0 + wm + mi * 16 + gr + half * 8;
                    float2 v = make_float2(acc[mi][ni][half * 2],
                                           acc[mi][ni][half * 2 + 1]);
                    float2* cp = (float2*)&C[(size_t)row * ldc + col];
                    if (MODE == 2) {
                        float2 o = *cp;
                        v.x += o.x; v.y += o.y;
                    }
                    *cp = v;
                }
            }
        }
    }
}

// ---------------------------------------------------------------------------
// Depthwise causal conv (D_CONV=4) + SiLU, float4; also resets lookback flags
// ---------------------------------------------------------------------------
__global__ void conv_silu_kernel(const float* __restrict__ xz,
                                 const float* __restrict__ cw,
                                 const float* __restrict__ cb,
                                 float* __restrict__ xc,
                                 int* __restrict__ flags)
{
    GRID_WAIT();
    const int DV = D_INNER / 4;
    int idx = blockIdx.x * blockDim.x + threadIdx.x;
    if (idx < NFLAGS) flags[idx] = 0;
    if (idx >= NTOK * DV) return;
    int d4 = idx & (DV - 1);
    int t  = idx >> 7;
    int l  = t & (SEQLEN - 1);
    int d  = d4 * 4;

    const float4* row = (const float4*)xz + (size_t)t * (2 * D_INNER / 4) + d4;
    const int RS = 2 * D_INNER / 4;
    float4 z4 = make_float4(0.f, 0.f, 0.f, 0.f);
    float4 r0 = (l >= 3) ? row[-3 * RS] : z4;
    float4 r1 = (l >= 2) ? row[-2 * RS] : z4;
    float4 r2 = (l >= 1) ? row[-1 * RS] : z4;
    float4 r3 = row[0];

    const float4* cw4 = (const float4*)cw;
    float4 w0 = cw4[d + 0], w1 = cw4[d + 1], w2 = cw4[d + 2], w3 = cw4[d + 3];
    float4 bb = ((const float4*)cb)[d4];

    float4 o;
    o.x = bb.x + r0.x * w0.x + r1.x * w0.y + r2.x * w0.z + r3.x * w0.w;
    o.y = bb.y + r0.y * w1.x + r1.y * w1.y + r2.y * w1.z + r3.y * w1.w;
    o.z = bb.z + r0.z * w2.x + r1.z * w2.y + r2.z * w2.z + r3.z * w2.w;
    o.w = bb.w + r0.w * w3.x + r1.w * w3.y + r2.w * w3.z + r3.w * w3.w;

    o.x = o.x / (1.f + __expf(-o.x));
    o.y = o.y / (1.f + __expf(-o.y));
    o.z = o.z / (1.f + __expf(-o.z));
    o.w = o.w / (1.f + __expf(-o.w));

    ((float4*)xc)[idx] = o;
}

// ---------------------------------------------------------------------------
// Fused selective scan (lookback). Stages dbl by summing the XP_SK split-K
// partial slices inline (z ascending — identical FP order to the old reduce).
// ---------------------------------------------------------------------------
__global__ __launch_bounds__(256)
void scan_fused(const float* __restrict__ part,
                const float* __restrict__ xc,
                const float* __restrict__ xz,
                const float* __restrict__ A_log,
                const float* __restrict__ dpw,
                const float* __restrict__ dpb,
                const float* __restrict__ Dp,
                float* __restrict__ cA,
                float* __restrict__ cH,
                int*   __restrict__ flags,
                float* __restrict__ y)
{
    GRID_WAIT();
    __shared__ float s_dt[CLEN * 16];
    __shared__ float s_B [CLEN * 16];
    __shared__ float s_C [CLEN * 16];
    __shared__ float s_xc[CLEN * 16];
    __shared__ float s_dl[CLEN * 16];
    __shared__ float s_pw[16 * 17];
    float* s_y = s_dt;

    int dg = blockIdx.x & 31;
    int c  = (blockIdx.x >> 5) & (NCHUNK - 1);
    int b  = blockIdx.x >> 10;
    int tid = threadIdx.x;
    int n  = tid & 15;
    int dl = tid >> 4;
    int d  = dg * 16 + dl;
    int l0 = c * CLEN;

    const int NV = NTOK * DBL_COLS / 4;   // float4 count per slice
    const float4* part4 = (const float4*)part + ((size_t)b * SEQLEN + l0) * 12;
    const float*  xc_p  = xc + ((size_t)b * SEQLEN + l0) * D_INNER + dg * 16;

    // dbl staging with inline split-K reduce: 64 rows x 12 float4
    for (int idx = tid; idx < CLEN * 12; idx += 256) {
        int l = idx / 12, g = idx % 12;
        float4 v = part4[l * 12 + g];
        #pragma unroll
        for (int z = 1; z < XP_SK; z++) {
            float4 p = part4[(size_t)z * NV + l * 12 + g];
            v.x += p.x; v.y += p.y; v.z += p.z; v.w += p.w;
        }
        int cc = g * 4;
        float* dst = (cc < 16) ? &s_dt[l * 16 + cc]
                   : (cc < 32) ? &s_B [l * 16 + cc - 16]
                               : &s_C [l * 16 + cc - 32];
        *(float4*)dst = v;
    }
    {
        int l = tid >> 2, g = tid & 3;
        *(float4*)&s_xc[l * 16 + g * 4] =
            *(const float4*)&xc_p[(size_t)l * D_INNER + g * 4];
    }
    {
        int rr = tid >> 4, cc = tid & 15;
        s_pw[rr * 17 + cc] = dpw[(size_t)(dg * 16 + rr) * DT_RANK + cc];
    }
    __syncthreads();

    // delta (consumes s_dt)
    for (int idx = tid; idx < CLEN * 16; idx += 256) {
        int l = idx >> 4, dd = idx & 15;
        float acc = dpb[dg * 16 + dd];
        #pragma unroll
        for (int r = 0; r < 16; r++)
            acc += s_dt[l * 16 + r] * s_pw[dd * 17 + r];
        s_dl[l * 16 + dd] = (acc > 20.f) ? acc : log1pf(__expf(acc));
    }
    __syncthreads();

    float Adn = -__expf(A_log[d * D_STATE + n]);

    // local scan
    float hloc = 0.f, P = 1.f;
    #pragma unroll 8
    for (int l = 0; l < CLEN; l++) {
        float dv = s_dl[l * 16 + dl];
        float a  = __expf(dv * Adn);
        hloc = a * hloc + (dv * s_xc[l * 16 + dl]) * s_B[l * 16 + n];
        P *= a;
    }

    // publish
    size_t col_base = (((size_t)b * NCHUNK) * D_INNER + d) * D_STATE + n;
    size_t cstride  = (size_t)D_INNER * D_STATE;
    cA[col_base + (size_t)c * cstride] = P;
    cH[col_base + (size_t)c * cstride] = hloc;
    __threadfence();
    __syncthreads();
    if (tid == 0) {
        int* fp = &flags[(b * NCHUNK + c) * 32 + dg];
        asm volatile("st.release.gpu.b32 [%0], %1;" :: "l"(fp), "r"(1) : "memory");
    }

    // lookback
    float h = 0.f;
    if (c > 0) {
        if (tid < c) {
            const int* fp = &flags[(b * NCHUNK + tid) * 32 + dg];
            int v;
            do {
                asm volatile("ld.acquire.gpu.b32 %0, [%1];" : "=r"(v) : "l"(fp) : "memory");
            } while (v == 0);
        }
        __syncthreads();
        for (int j = 0; j < c; j++) {
            size_t o = col_base + (size_t)j * cstride;
            h = cA[o] * h + cH[o];
        }
    }

    // replay + n-reduce
    #pragma unroll 4
    for (int l = 0; l < CLEN; l++) {
        float dv = s_dl[l * 16 + dl];
        h = __expf(dv * Adn) * h + (dv * s_xc[l * 16 + dl]) * s_B[l * 16 + n];
        float p = h * s_C[l * 16 + n];
        p += __shfl_xor_sync(0xffffffffu, p, 8);
        p += __shfl_xor_sync(0xffffffffu, p, 4);
        p += __shfl_xor_sync(0xffffffffu, p, 2);
        p += __shfl_xor_sync(0xffffffffu, p, 1);
        if (n == 0) s_y[l * 16 + dl] = p;
    }
    __syncthreads();

    // gate + write (float4)
    const float* z_p = xz + ((size_t)b * SEQLEN + l0) * 2 * D_INNER + D_INNER + dg * 16;
    float*       y_p = y  + ((size_t)b * SEQLEN + l0) * D_INNER + dg * 16;
    const float4 Dv = ((const float4*)Dp)[dg * 4 + (tid & 3)];
    {
        int l = tid >> 2, g = tid & 3;
        float4 z4 = *(const float4*)&z_p[(size_t)l * 2 * D_INNER + g * 4];
        float4 yv = *(float4*)&s_y[l * 16 + g * 4];
        float4 xv = *(float4*)&s_xc[l * 16 + g * 4];
        float4 o;
        o.x = (yv.x + xv.x * Dv.x) * (z4.x / (1.f + __expf(-z4.x)));
        o.y = (yv.y + xv.y * Dv.y) * (z4.y / (1.f + __expf(-z4.y)));
        o.z = (yv.z + xv.z * Dv.z) * (z4.z / (1.f + __expf(-z4.z)));
        o.w = (yv.w + xv.w * Dv.w) * (z4.w / (1.f + __expf(-z4.w)));
        *(float4*)&y_p[(size_t)l * D_INNER + g * 4] = o;
    }
}

// ---------------------------------------------------------------------------
// PDL launch helper
// ---------------------------------------------------------------------------
template <typename F, typename... Args>
static void launch_pdl(F* kern, dim3 grid, dim3 block, Args... args)
{
    cudaLaunchConfig_t cfg = {};
    cfg.gridDim = grid;
    cfg.blockDim = block;
    cfg.dynamicSmemBytes = 0;
    cudaLaunchAttribute attr[1];
    attr[0].id = cudaLaunchAttributeProgrammaticStreamSerialization;
    attr[0].val.programmaticStreamSerializationAllowed = 1;
    cfg.attrs = attr;
    cfg.numAttrs = 1;
    cudaLaunchKernelEx(&cfg, kern, args...);
}

// ---------------------------------------------------------------------------
// Launcher
// ---------------------------------------------------------------------------
extern "C" void kernel_launch(void* const* d_in, const int* in_sizes, int n_in,
                              void* d_out, int out_size)
{
    const float* x_in = (const float*)d_in[0];
    const float* ln_w = (const float*)d_in[1];
    const float* ln_b = (const float*)d_in[2];
    const float* ipw  = (const float*)d_in[3];
    const float* cw   = (const float*)d_in[4];
    const float* cb   = (const float*)d_in[5];
    const float* xpw  = (const float*)d_in[6];
    const float* dpw  = (const float*)d_in[7];
    const float* dpb  = (const float*)d_in[8];
    const float* alog = (const float*)d_in[9];
    const float* dpar = (const float*)d_in[10];
    const float* opw  = (const float*)d_in[11];
    float* xbuf = (float*)d_out;

    float *p_h, *p_xz, *p_xc, *p_part, *p_y, *p_cA, *p_cH;
    int* p_flag;
    cudaGetSymbolAddress((void**)&p_h,    g_h);
    cudaGetSymbolAddress((void**)&p_xz,   g_xz);
    cudaGetSymbolAddress((void**)&p_xc,   g_xc);
    cudaGetSymbolAddress((void**)&p_part, g_part);
    cudaGetSymbolAddress((void**)&p_y,    g_y);
    cudaGetSymbolAddress((void**)&p_cA,   g_cA);
    cudaGetSymbolAddress((void**)&p_cH,   g_cH);
    cudaGetSymbolAddress((void**)&p_flag, g_flag);

    cudaMemcpyAsync(xbuf, x_in, (size_t)NTOK * D_MODEL * sizeof(float),
                    cudaMemcpyDeviceToDevice);

    const int SCAN_BLOCKS = BATCH * NCHUNK * 32;
    const int CONV_BLOCKS = (NTOK * (D_INNER / 4) + 255) / 256;

    for (int layer = 0; layer < DEPTH; layer++) {
        const float* l_lnw  = ln_w + layer * D_MODEL;
        const float* l_lnb  = ln_b + layer * D_MODEL;
        const float* l_ipw  = ipw  + (size_t)layer * 2 * D_INNER * D_MODEL;
        const float* l_cw   = cw   + (size_t)layer * D_INNER * D_CONV;
        const float* l_cb   = cb   + (size_t)layer * D_INNER;
        const float* l_xpw  = xpw  + (size_t)layer * DBL_COLS * D_INNER;
        const float* l_dpw  = dpw  + (size_t)layer * D_INNER * DT_RANK;
        const float* l_dpb  = dpb  + (size_t)layer * D_INNER;
        const float* l_alog = alog + (size_t)layer * D_INNER * D_STATE;
        const float* l_dpar = dpar + (size_t)layer * D_INNER;
        const float* l_opw  = opw  + (size_t)layer * D_MODEL * D_INNER;

        // 1. LayerNorm
        launch_pdl(ln_kernel, dim3(NTOK), dim3(D_MODEL),
                   (const float*)xbuf, l_lnw, l_lnb, p_h);

        // 2. in_proj: BM=128, BN=64 -> 512 CTAs
        launch_pdl(gemm_tf32<0, 2, 4>, dim3(16, NTOK / 128, 1), dim3(256),
                   (const float*)p_h, D_MODEL, l_ipw, D_MODEL,
                   p_xz, 2 * D_INNER, 2 * D_INNER, D_MODEL, (size_t)0);

        // 3. conv + silu (float4) + flag reset
        launch_pdl(conv_silu_kernel, dim3(CONV_BLOCKS), dim3(256),
                   (const float*)p_xz, l_cw, l_cb, p_xc, p_flag);

        // 4. x_proj split-K=8 -> 256 CTAs (partials only)
        launch_pdl(gemm_tf32<0, 2, 4>, dim3(1, NTOK / 128, XP_SK), dim3(256),
                   (const float*)p_xc, D_INNER, l_xpw, D_INNER,
                   p_part, DBL_COLS, DBL_COLS, D_INNER / XP_SK,
                   (size_t)NTOK * DBL_COLS);

        // 5. fused scan (split-K reduce inlined in staging)
        launch_pdl(scan_fused, dim3(SCAN_BLOCKS), dim3(256),
                   (const float*)p_part, (const float*)p_xc,
                   (const float*)p_xz, l_alog, l_dpw, l_dpb, l_dpar,
                   p_cA, p_cH, p_flag, p_y);

        // 6. out_proj + residual: BM=128 -> 128 CTAs
        launch_pdl(gemm_tf32<2, 2, 4>, dim3(4, NTOK / 128, 1), dim3(256),
                   (const float*)p_y, D_INNER, l_opw, D_INNER,
                   xbuf, D_MODEL, D_MODEL, D_INNER, (size_t)0);
    }
}

// round 13
// speedup vs baseline: 1.3767x; 1.0454x over previous
#include <cuda_runtime.h>
#include <cuda_bf16.h>
#include <math.h>
#include <stdint.h>

// ---------------------------------------------------------------------------
#define D_MODEL   256
#define DEPTH     2
#define D_INNER   512
#define D_STATE   16
#define D_CONV    4
#define DT_RANK   16
#define BATCH     2
#define SEQLEN    2048
#define NTOK      (BATCH * SEQLEN)          // 4096
#define DBL_COLS  (DT_RANK + 2 * D_STATE)   // 48

#define NCHUNK    32
#define CLEN      (SEQLEN / NCHUNK)         // 64
#define XP_SK     8
#define NFLAGS    (BATCH * NCHUNK * 32)

#define GRID_WAIT() asm volatile("griddepcontrol.wait;" ::: "memory")

// ---------------------------------------------------------------------------
// Scratch
// ---------------------------------------------------------------------------
__device__ float g_h    [NTOK * D_MODEL];
__device__ float g_xz   [NTOK * 2 * D_INNER];
__device__ float g_xc   [NTOK * D_INNER];
__device__ float g_dbl  [NTOK * DBL_COLS];
__device__ float g_part [XP_SK * NTOK * DBL_COLS];
__device__ float g_y    [NTOK * D_INNER];
__device__ float g_cA   [BATCH * NCHUNK * D_INNER * D_STATE];
__device__ float g_cH   [BATCH * NCHUNK * D_INNER * D_STATE];
__device__ int   g_flag [NFLAGS];

// ---------------------------------------------------------------------------
// cp.async helpers
// ---------------------------------------------------------------------------
__device__ __forceinline__ uint32_t smem_u32(const void* p) {
    uint32_t a;
    asm("{.reg .u64 t; cvta.to.shared.u64 t, %1; cvt.u32.u64 %0, t;}"
        : "=r"(a) : "l"(p));
    return a;
}
__device__ __forceinline__ void cp_async16(void* dst, const void* src) {
    asm volatile("cp.async.ca.shared.global [%0], [%1], 16;"
                 :: "r"(smem_u32(dst)), "l"(src));
}
__device__ __forceinline__ void cp_async16_z(void* dst, const void* src, bool ok) {
    int sz = ok ? 16 : 0;
    asm volatile("cp.async.ca.shared.global [%0], [%1], 16, %2;"
                 :: "r"(smem_u32(dst)), "l"(src), "r"(sz));
}
#define CP_COMMIT() asm volatile("cp.async.commit_group;")
#define CP_WAIT1()  asm volatile("cp.async.wait_group 1;")
#define CP_WAIT0()  asm volatile("cp.async.wait_group 0;")

// ---------------------------------------------------------------------------
// LayerNorm: warp per token, float4. Grid = NTOK/8, block 256.
// ---------------------------------------------------------------------------
__global__ void ln_kernel(const float* __restrict__ x,
                          const float* __restrict__ w,
                          const float* __restrict__ b,
                          float* __restrict__ out)
{
    GRID_WAIT();
    int lane = threadIdx.x & 31;
    int warp = threadIdx.x >> 5;
    int t = blockIdx.x * 8 + warp;

    const float4* x4 = (const float4*)x;
    float4*       o4 = (float4*)out;
    const float4* w4 = (const float4*)w;
    const float4* b4 = (const float4*)b;

    float4 a  = x4[(size_t)t * 64 + lane];
    float4 bb = x4[(size_t)t * 64 + 32 + lane];
    float s = a.x + a.y + a.z + a.w + bb.x + bb.y + bb.z + bb.w;
    float q = a.x * a.x + a.y * a.y + a.z * a.z + a.w * a.w
            + bb.x * bb.x + bb.y * bb.y + bb.z * bb.z + bb.w * bb.w;
    #pragma unroll
    for (int o = 16; o > 0; o >>= 1) {
        s += __shfl_xor_sync(0xffffffffu, s, o);
        q += __shfl_xor_sync(0xffffffffu, q, o);
    }
    float mu  = s * (1.f / D_MODEL);
    float var = q * (1.f / D_MODEL) - mu * mu;
    float inv = rsqrtf(var + 1e-5f);

    float4 w1 = w4[lane], w2 = w4[32 + lane];
    float4 b1 = b4[lane], b2 = b4[32 + lane];
    float4 o1, o2;
    o1.x = (a.x - mu) * inv * w1.x + b1.x;
    o1.y = (a.y - mu) * inv * w1.y + b1.y;
    o1.z = (a.z - mu) * inv * w1.z + b1.z;
    o1.w = (a.w - mu) * inv * w1.w + b1.w;
    o2.x = (bb.x - mu) * inv * w2.x + b2.x;
    o2.y = (bb.y - mu) * inv * w2.y + b2.y;
    o2.z = (bb.z - mu) * inv * w2.z + b2.z;
    o2.w = (bb.w - mu) * inv * w2.w + b2.w;
    o4[(size_t)t * 64 + lane]      = o1;
    o4[(size_t)t * 64 + 32 + lane] = o2;
}

// ---------------------------------------------------------------------------
// tf32 tensor-core GEMM, 3-stage cp.async pipeline, race-fixed, with PDL
// weight prologue: W-tile for k0=0 is issued BEFORE griddepcontrol.wait
// (weights are const inputs). Commit groups: {W0}, {A0}, {T1}, {T2}, ...
// -> the wait_group 1/0 scheme keeps tile i complete before its use.
// C[M,N] = A[M,K] @ W[N,K]^T.  MODE 0: store | MODE 2: C += acc.
// BM=64*MT, BN=16*NI. 256 threads = 8 warps (4Mx2N). blockIdx.z = split-K.
// ---------------------------------------------------------------------------
template <int MODE, int MT, int NI>
__global__ __launch_bounds__(256)
void gemm_tf32(const float* __restrict__ A, int lda,
               const float* __restrict__ W, int ldw,
               float*       __restrict__ C, int ldc,
               int N, int K, size_t csplit)
{
    const int BM = 64 * MT, BN = 16 * NI, BK = 16, LDS = 20, S = 3;
    __shared__ uint32_t As[S][BM * LDS];
    __shared__ uint32_t Bs[S][BN * LDS];

    A += (size_t)blockIdx.z * K;
    C += (size_t)blockIdx.z * csplit;

    int tid  = threadIdx.x;
    int lane = tid & 31;
    int warp = tid >> 5;
    int m0 = blockIdx.y * BM;
    int n0 = blockIdx.x * BN;
    int wm = (warp >> 1) * 16 * MT;
    int wn = (warp & 1) * 8 * NI;
    int gr = lane >> 2;
    int gc = lane & 3;

    float acc[MT][NI][4];
    #pragma unroll
    for (int mi = 0; mi < MT; mi++)
        #pragma unroll
        for (int ni = 0; ni < NI; ni++)
            #pragma unroll
            for (int e = 0; e < 4; e++) acc[mi][ni][e] = 0.f;

    int lrow = tid >> 2;
    int lcol = (tid & 3) * 4;

    auto issueW = [&](int ti) {
        int buf = ti % S;
        int k0  = ti * BK;
        #pragma unroll
        for (int h = 0; h < NI / 4; h++) {
            int r = lrow + h * 64;
            bool ok = (n0 + r) < N;
            const float* src = ok ? &W[(size_t)(n0 + r) * ldw + k0 + lcol] : W;
            cp_async16_z(&Bs[buf][r * LDS + lcol], src, ok);
        }
    };
    auto issueA = [&](int ti) {
        int buf = ti % S;
        int k0  = ti * BK;
        #pragma unroll
        for (int h = 0; h < MT; h++) {
            int r = lrow + h * 64;
            cp_async16(&As[buf][r * LDS + lcol],
                       &A[(size_t)(m0 + r) * lda + k0 + lcol]);
        }
    };

    int nk = K / BK;
    // PDL prologue: weight tile 0 before waiting on the upstream kernel.
    issueW(0); CP_COMMIT();
    GRID_WAIT();
    issueA(0); CP_COMMIT();
    issueA(1); issueW(1); CP_COMMIT();

    for (int i = 0; i < nk; i++) {
        if (i + 1 < nk) { CP_WAIT1(); } else { CP_WAIT0(); }
        __syncthreads();
        if (i + 2 < nk) { issueA(i + 2); issueW(i + 2); CP_COMMIT(); }
        int buf = i % S;

        #pragma unroll
        for (int ks = 0; ks < BK; ks += 8) {
            uint32_t a[MT][4], b[NI][2];
            #pragma unroll
            for (int mi = 0; mi < MT; mi++) {
                int rb = wm + mi * 16 + gr;
                a[mi][0] = As[buf][rb * LDS + ks + gc];
                a[mi][1] = As[buf][(rb + 8) * LDS + ks + gc];
                a[mi][2] = As[buf][rb * LDS + ks + gc + 4];
                a[mi][3] = As[buf][(rb + 8) * LDS + ks + gc + 4];
            }
            #pragma unroll
            for (int ni = 0; ni < NI; ni++) {
                int rb = wn + ni * 8 + gr;
                b[ni][0] = Bs[buf][rb * LDS + ks + gc];
                b[ni][1] = Bs[buf][rb * LDS + ks + gc + 4];
            }
            #pragma unroll
            for (int mi = 0; mi < MT; mi++)
                #pragma unroll
                for (int ni = 0; ni < NI; ni++)
                    asm volatile(
                        "mma.sync.aligned.m16n8k8.row.col.f32.tf32.tf32.f32 "
                        "{%0,%1,%2,%3}, {%4,%5,%6,%7}, {%8,%9}, {%0,%1,%2,%3};"
                        : "+f"(acc[mi][ni][0]), "+f"(acc[mi][ni][1]),
                          "+f"(acc[mi][ni][2]), "+f"(acc[mi][ni][3])
                        : "r"(a[mi][0]), "r"(a[mi][1]), "r"(a[mi][2]), "r"(a[mi][3]),
                          "r"(b[ni][0]), "r"(b[ni][1]));
        }
    }

    #pragma unroll
    for (int mi = 0; mi < MT; mi++) {
        #pragma unroll
        for (int ni = 0; ni < NI; ni++) {
            int col = n0 + wn + ni * 8 + gc * 2;
            if (col < N) {
                #pragma unroll
                for (int half = 0; half < 2; half++) {
                    int row = m0 + wm + mi * 16 + gr + half * 8;
                    float2 v = make_float2(acc[mi][ni][half * 2],
                                           acc[mi][ni][half * 2 + 1]);
                    float2* cp = (float2*)&C[(size_t)row * ldc + col];
                    if (MODE == 2) {
                        float2 o = *cp;
                        v.x += o.x; v.y += o.y;
                    }
                    *cp = v;
                }
            }
        }
    }
}

// ---------------------------------------------------------------------------
// Reduce x_proj split-K partials (float4) + zero lookback flags
// ---------------------------------------------------------------------------
__global__ void reduce_dbl(const float4* __restrict__ part,
                           float4* __restrict__ dbl,
                           int* __restrict__ flags)
{
    GRID_WAIT();
    int i = blockIdx.x * 256 + threadIdx.x;
    if (i < NFLAGS) flags[i] = 0;
    const int NV = NTOK * DBL_COLS / 4;
    if (i < NV) {
        float4 s = part[i];
        #pragma unroll
        for (int z = 1; z < XP_SK; z++) {
            float4 p = part[(size_t)z * NV + i];
            s.x += p.x; s.y += p.y; s.z += p.z; s.w += p.w;
        }
        dbl[i] = s;
    }
}

// ---------------------------------------------------------------------------
// Depthwise causal conv (D_CONV=4) + SiLU, float4 over channels
// ---------------------------------------------------------------------------
__global__ void conv_silu_kernel(const float* __restrict__ xz,
                                 const float* __restrict__ cw,
                                 const float* __restrict__ cb,
                                 float* __restrict__ xc)
{
    GRID_WAIT();
    const int DV = D_INNER / 4;
    int idx = blockIdx.x * blockDim.x + threadIdx.x;
    if (idx >= NTOK * DV) return;
    int d4 = idx & (DV - 1);
    int t  = idx >> 7;
    int l  = t & (SEQLEN - 1);
    int d  = d4 * 4;

    const float4* row = (const float4*)xz + (size_t)t * (2 * D_INNER / 4) + d4;
    const int RS = 2 * D_INNER / 4;
    float4 z4 = make_float4(0.f, 0.f, 0.f, 0.f);
    float4 r0 = (l >= 3) ? row[-3 * RS] : z4;
    float4 r1 = (l >= 2) ? row[-2 * RS] : z4;
    float4 r2 = (l >= 1) ? row[-1 * RS] : z4;
    float4 r3 = row[0];

    const float4* cw4 = (const float4*)cw;
    float4 w0 = cw4[d + 0], w1 = cw4[d + 1], w2 = cw4[d + 2], w3 = cw4[d + 3];
    float4 bb = ((const float4*)cb)[d4];

    float4 o;
    o.x = bb.x + r0.x * w0.x + r1.x * w0.y + r2.x * w0.z + r3.x * w0.w;
    o.y = bb.y + r0.y * w1.x + r1.y * w1.y + r2.y * w1.z + r3.y * w1.w;
    o.z = bb.z + r0.z * w2.x + r1.z * w2.y + r2.z * w2.z + r3.z * w2.w;
    o.w = bb.w + r0.w * w3.x + r1.w * w3.y + r2.w * w3.z + r3.w * w3.w;

    o.x = o.x / (1.f + __expf(-o.x));
    o.y = o.y / (1.f + __expf(-o.y));
    o.z = o.z / (1.f + __expf(-o.z));
    o.w = o.w / (1.f + __expf(-o.w));

    ((float4*)xc)[idx] = o;
}

// ---------------------------------------------------------------------------
// Fused selective scan (lookback), float4 staging, batched lookback combine.
// ---------------------------------------------------------------------------
__global__ __launch_bounds__(256)
void scan_fused(const float* __restrict__ dbl,
                const float* __restrict__ xc,
                const float* __restrict__ xz,
                const float* __restrict__ A_log,
                const float* __restrict__ dpw,
                const float* __restrict__ dpb,
                const float* __restrict__ Dp,
                float* __restrict__ cA,
                float* __restrict__ cH,
                int*   __restrict__ flags,
                float* __restrict__ y)
{
    GRID_WAIT();
    __shared__ float s_dt[CLEN * 16];
    __shared__ float s_B [CLEN * 16];
    __shared__ float s_C [CLEN * 16];
    __shared__ float s_xc[CLEN * 16];
    __shared__ float s_dl[CLEN * 16];
    __shared__ float s_pw[16 * 17];
    float* s_y = s_dt;

    int dg = blockIdx.x & 31;
    int c  = (blockIdx.x >> 5) & (NCHUNK - 1);
    int b  = blockIdx.x >> 10;
    int tid = threadIdx.x;
    int n  = tid & 15;
    int dl = tid >> 4;
    int d  = dg * 16 + dl;
    int l0 = c * CLEN;

    const float4* dbl4 = (const float4*)(dbl + ((size_t)b * SEQLEN + l0) * DBL_COLS);
    const float*  xc_p = xc + ((size_t)b * SEQLEN + l0) * D_INNER + dg * 16;

    for (int idx = tid; idx < CLEN * 12; idx += 256) {
        int l = idx / 12, g = idx % 12;
        float4 v = dbl4[l * 12 + g];
        int cc = g * 4;
        float* dst = (cc < 16) ? &s_dt[l * 16 + cc]
                   : (cc < 32) ? &s_B [l * 16 + cc - 16]
                               : &s_C [l * 16 + cc - 32];
        *(float4*)dst = v;
    }
    {
        int l = tid >> 2, g = tid & 3;
        *(float4*)&s_xc[l * 16 + g * 4] =
            *(const float4*)&xc_p[(size_t)l * D_INNER + g * 4];
    }
    {
        int rr = tid >> 4, cc = tid & 15;
        s_pw[rr * 17 + cc] = dpw[(size_t)(dg * 16 + rr) * DT_RANK + cc];
    }
    __syncthreads();

    for (int idx = tid; idx < CLEN * 16; idx += 256) {
        int l = idx >> 4, dd = idx & 15;
        float acc = dpb[dg * 16 + dd];
        #pragma unroll
        for (int r = 0; r < 16; r++)
            acc += s_dt[l * 16 + r] * s_pw[dd * 17 + r];
        s_dl[l * 16 + dd] = (acc > 20.f) ? acc : log1pf(__expf(acc));
    }
    __syncthreads();

    float Adn = -__expf(A_log[d * D_STATE + n]);

    float hloc = 0.f, P = 1.f;
    #pragma unroll 8
    for (int l = 0; l < CLEN; l++) {
        float dv = s_dl[l * 16 + dl];
        float a  = __expf(dv * Adn);
        hloc = a * hloc + (dv * s_xc[l * 16 + dl]) * s_B[l * 16 + n];
        P *= a;
    }

    size_t col_base = (((size_t)b * NCHUNK) * D_INNER + d) * D_STATE + n;
    size_t cstride  = (size_t)D_INNER * D_STATE;
    cA[col_base + (size_t)c * cstride] = P;
    cH[col_base + (size_t)c * cstride] = hloc;
    __threadfence();
    __syncthreads();
    if (tid == 0) {
        int* fp = &flags[(b * NCHUNK + c) * 32 + dg];
        asm volatile("st.release.gpu.b32 [%0], %1;" :: "l"(fp), "r"(1) : "memory");
    }

    // lookback: wait, then 4-way batched combine (same FMA order as serial)
    float h = 0.f;
    if (c > 0) {
        if (tid < c) {
            const int* fp = &flags[(b * NCHUNK + tid) * 32 + dg];
            int v;
            do {
                asm volatile("ld.acquire.gpu.b32 %0, [%1];" : "=r"(v) : "l"(fp) : "memory");
            } while (v == 0);
        }
        __syncthreads();
        int j = 0;
        for (; j + 4 <= c; j += 4) {
            size_t o0 = col_base + (size_t)(j + 0) * cstride;
            size_t o1 = col_base + (size_t)(j + 1) * cstride;
            size_t o2 = col_base + (size_t)(j + 2) * cstride;
            size_t o3 = col_base + (size_t)(j + 3) * cstride;
            float a0 = cA[o0], h0 = cH[o0];
            float a1 = cA[o1], h1 = cH[o1];
            float a2 = cA[o2], h2 = cH[o2];
            float a3 = cA[o3], h3 = cH[o3];
            h = a0 * h + h0;
            h = a1 * h + h1;
            h = a2 * h + h2;
            h = a3 * h + h3;
        }
        for (; j < c; j++) {
            size_t o = col_base + (size_t)j * cstride;
            h = cA[o] * h + cH[o];
        }
    }

    #pragma unroll 4
    for (int l = 0; l < CLEN; l++) {
        float dv = s_dl[l * 16 + dl];
        h = __expf(dv * Adn) * h + (dv * s_xc[l * 16 + dl]) * s_B[l * 16 + n];
        float p = h * s_C[l * 16 + n];
        p += __shfl_xor_sync(0xffffffffu, p, 8);
        p += __shfl_xor_sync(0xffffffffu, p, 4);
        p += __shfl_xor_sync(0xffffffffu, p, 2);
        p += __shfl_xor_sync(0xffffffffu, p, 1);
        if (n == 0) s_y[l * 16 + dl] = p;
    }
    __syncthreads();

    const float* z_p = xz + ((size_t)b * SEQLEN + l0) * 2 * D_INNER + D_INNER + dg * 16;
    float*       y_p = y  + ((size_t)b * SEQLEN + l0) * D_INNER + dg * 16;
    const float4 Dv = ((const float4*)Dp)[dg * 4 + (tid & 3)];
    {
        int l = tid >> 2, g = tid & 3;
        float4 z4 = *(const float4*)&z_p[(size_t)l * 2 * D_INNER + g * 4];
        float4 yv = *(float4*)&s_y[l * 16 + g * 4];
        float4 xv = *(float4*)&s_xc[l * 16 + g * 4];
        float4 o;
        o.x = (yv.x + xv.x * Dv.x) * (z4.x / (1.f + __expf(-z4.x)));
        o.y = (yv.y + xv.y * Dv.y) * (z4.y / (1.f + __expf(-z4.y)));
        o.z = (yv.z + xv.z * Dv.z) * (z4.z / (1.f + __expf(-z4.z)));
        o.w = (yv.w + xv.w * Dv.w) * (z4.w / (1.f + __expf(-z4.w)));
        *(float4*)&y_p[(size_t)l * D_INNER + g * 4] = o;
    }
}

// ---------------------------------------------------------------------------
// PDL launch helper
// ---------------------------------------------------------------------------
template <typename F, typename... Args>
static void launch_pdl(F* kern, dim3 grid, dim3 block, Args... args)
{
    cudaLaunchConfig_t cfg = {};
    cfg.gridDim = grid;
    cfg.blockDim = block;
    cfg.dynamicSmemBytes = 0;
    cudaLaunchAttribute attr[1];
    attr[0].id = cudaLaunchAttributeProgrammaticStreamSerialization;
    attr[0].val.programmaticStreamSerializationAllowed = 1;
    cfg.attrs = attr;
    cfg.numAttrs = 1;
    cudaLaunchKernelEx(&cfg, kern, args...);
}

// ---------------------------------------------------------------------------
// Launcher
// ---------------------------------------------------------------------------
extern "C" void kernel_launch(void* const* d_in, const int* in_sizes, int n_in,
                              void* d_out, int out_size)
{
    const float* x_in = (const float*)d_in[0];
    const float* ln_w = (const float*)d_in[1];
    const float* ln_b = (const float*)d_in[2];
    const float* ipw  = (const float*)d_in[3];
    const float* cw   = (const float*)d_in[4];
    const float* cb   = (const float*)d_in[5];
    const float* xpw  = (const float*)d_in[6];
    const float* dpw  = (const float*)d_in[7];
    const float* dpb  = (const float*)d_in[8];
    const float* alog = (const float*)d_in[9];
    const float* dpar = (const float*)d_in[10];
    const float* opw  = (const float*)d_in[11];
    float* xbuf = (float*)d_out;

    float *p_h, *p_xz, *p_xc, *p_dbl, *p_part, *p_y, *p_cA, *p_cH;
    int* p_flag;
    cudaGetSymbolAddress((void**)&p_h,    g_h);
    cudaGetSymbolAddress((void**)&p_xz,   g_xz);
    cudaGetSymbolAddress((void**)&p_xc,   g_xc);
    cudaGetSymbolAddress((void**)&p_dbl,  g_dbl);
    cudaGetSymbolAddress((void**)&p_part, g_part);
    cudaGetSymbolAddress((void**)&p_y,    g_y);
    cudaGetSymbolAddress((void**)&p_cA,   g_cA);
    cudaGetSymbolAddress((void**)&p_cH,   g_cH);
    cudaGetSymbolAddress((void**)&p_flag, g_flag);

    cudaMemcpyAsync(xbuf, x_in, (size_t)NTOK * D_MODEL * sizeof(float),
                    cudaMemcpyDeviceToDevice);

    const int SCAN_BLOCKS = BATCH * NCHUNK * 32;
    const int CONV_BLOCKS = (NTOK * (D_INNER / 4) + 255) / 256;

    for (int layer = 0; layer < DEPTH; layer++) {
        const float* l_lnw  = ln_w + layer * D_MODEL;
        const float* l_lnb  = ln_b + layer * D_MODEL;
        const float* l_ipw  = ipw  + (size_t)layer * 2 * D_INNER * D_MODEL;
        const float* l_cw   = cw   + (size_t)layer * D_INNER * D_CONV;
        const float* l_cb   = cb   + (size_t)layer * D_INNER;
        const float* l_xpw  = xpw  + (size_t)layer * DBL_COLS * D_INNER;
        const float* l_dpw  = dpw  + (size_t)layer * D_INNER * DT_RANK;
        const float* l_dpb  = dpb  + (size_t)layer * D_INNER;
        const float* l_alog = alog + (size_t)layer * D_INNER * D_STATE;
        const float* l_dpar = dpar + (size_t)layer * D_INNER;
        const float* l_opw  = opw  + (size_t)layer * D_MODEL * D_INNER;

        // 1. LayerNorm (warp per token)
        launch_pdl(ln_kernel, dim3(NTOK / 8), dim3(256),
                   (const float*)xbuf, l_lnw, l_lnb, p_h);

        // 2. in_proj: BM=128, BN=64 -> 512 CTAs
        launch_pdl(gemm_tf32<0, 2, 4>, dim3(16, NTOK / 128, 1), dim3(256),
                   (const float*)p_h, D_MODEL, l_ipw, D_MODEL,
                   p_xz, 2 * D_INNER, 2 * D_INNER, D_MODEL, (size_t)0);

        // 3. conv + silu (float4)
        launch_pdl(conv_silu_kernel, dim3(CONV_BLOCKS), dim3(256),
                   (const float*)p_xz, l_cw, l_cb, p_xc);

        // 4. x_proj split-K=8 -> 256 CTAs, then reduce (+ flag reset)
        launch_pdl(gemm_tf32<0, 2, 4>, dim3(1, NTOK / 128, XP_SK), dim3(256),
                   (const float*)p_xc, D_INNER, l_xpw, D_INNER,
                   p_part, DBL_COLS, DBL_COLS, D_INNER / XP_SK,
                   (size_t)NTOK * DBL_COLS);
        launch_pdl(reduce_dbl, dim3((NTOK * DBL_COLS / 4 + 255) / 256), dim3(256),
                   (const float4*)p_part, (float4*)p_dbl, p_flag);

        // 5. fused scan
        launch_pdl(scan_fused, dim3(SCAN_BLOCKS), dim3(256),
                   (const float*)p_dbl, (const float*)p_xc,
                   (const float*)p_xz, l_alog, l_dpw, l_dpb, l_dpar,
                   p_cA, p_cH, p_flag, p_y);

        // 6. out_proj + residual: BM=128 -> 128 CTAs
        launch_pdl(gemm_tf32<2, 2, 4>, dim3(4, NTOK / 128, 1), dim3(256),
                   (const float*)p_y, D_INNER, l_opw, D_INNER,
                   xbuf, D_MODEL, D_MODEL, D_INNER, (size_t)0);
    }
}

// round 14
// speedup vs baseline: 1.3772x; 1.0004x over previous
#include <cuda_runtime.h>
#include <cuda_bf16.h>
#include <math.h>
#include <stdint.h>

// ---------------------------------------------------------------------------
#define D_MODEL   256
#define DEPTH     2
#define D_INNER   512
#define D_STATE   16
#define D_CONV    4
#define DT_RANK   16
#define BATCH     2
#define SEQLEN    2048
#define NTOK      (BATCH * SEQLEN)          // 4096
#define DBL_COLS  (DT_RANK + 2 * D_STATE)   // 48

#define NCHUNK    32
#define CLEN      (SEQLEN / NCHUNK)         // 64
#define XP_SK     8
#define KSLICE    (D_INNER / XP_SK)         // 64
#define NFLAGS    (BATCH * NCHUNK * 32)

#define GRID_WAIT() asm volatile("griddepcontrol.wait;" ::: "memory")

// ---------------------------------------------------------------------------
// Scratch
// ---------------------------------------------------------------------------
__device__ float g_h    [NTOK * D_MODEL];
__device__ float g_xz   [NTOK * 2 * D_INNER];
__device__ float g_xc   [NTOK * D_INNER];
__device__ float g_dbl  [NTOK * DBL_COLS];
__device__ float g_part [XP_SK * NTOK * DBL_COLS];
__device__ float g_y    [NTOK * D_INNER];
__device__ float g_cA   [BATCH * NCHUNK * D_INNER * D_STATE];
__device__ float g_cH   [BATCH * NCHUNK * D_INNER * D_STATE];
__device__ int   g_flag [NFLAGS];

// ---------------------------------------------------------------------------
// cp.async helpers
// ---------------------------------------------------------------------------
__device__ __forceinline__ uint32_t smem_u32(const void* p) {
    uint32_t a;
    asm("{.reg .u64 t; cvta.to.shared.u64 t, %1; cvt.u32.u64 %0, t;}"
        : "=r"(a) : "l"(p));
    return a;
}
__device__ __forceinline__ void cp_async16(void* dst, const void* src) {
    asm volatile("cp.async.ca.shared.global [%0], [%1], 16;"
                 :: "r"(smem_u32(dst)), "l"(src));
}
__device__ __forceinline__ void cp_async16_z(void* dst, const void* src, bool ok) {
    int sz = ok ? 16 : 0;
    asm volatile("cp.async.ca.shared.global [%0], [%1], 16, %2;"
                 :: "r"(smem_u32(dst)), "l"(src), "r"(sz));
}
#define CP_COMMIT() asm volatile("cp.async.commit_group;")
#define CP_WAIT1()  asm volatile("cp.async.wait_group 1;")
#define CP_WAIT0()  asm volatile("cp.async.wait_group 0;")

// ---------------------------------------------------------------------------
// LayerNorm: warp per token, float4. Grid = NTOK/8, block 256.
// ---------------------------------------------------------------------------
__global__ void ln_kernel(const float* __restrict__ x,
                          const float* __restrict__ w,
                          const float* __restrict__ b,
                          float* __restrict__ out)
{
    GRID_WAIT();
    int lane = threadIdx.x & 31;
    int warp = threadIdx.x >> 5;
    int t = blockIdx.x * 8 + warp;

    const float4* x4 = (const float4*)x;
    float4*       o4 = (float4*)out;
    const float4* w4 = (const float4*)w;
    const float4* b4 = (const float4*)b;

    float4 a  = x4[(size_t)t * 64 + lane];
    float4 bb = x4[(size_t)t * 64 + 32 + lane];
    float s = a.x + a.y + a.z + a.w + bb.x + bb.y + bb.z + bb.w;
    float q = a.x * a.x + a.y * a.y + a.z * a.z + a.w * a.w
            + bb.x * bb.x + bb.y * bb.y + bb.z * bb.z + bb.w * bb.w;
    #pragma unroll
    for (int o = 16; o > 0; o >>= 1) {
        s += __shfl_xor_sync(0xffffffffu, s, o);
        q += __shfl_xor_sync(0xffffffffu, q, o);
    }
    float mu  = s * (1.f / D_MODEL);
    float var = q * (1.f / D_MODEL) - mu * mu;
    float inv = rsqrtf(var + 1e-5f);

    float4 w1 = w4[lane], w2 = w4[32 + lane];
    float4 b1 = b4[lane], b2 = b4[32 + lane];
    float4 o1, o2;
    o1.x = (a.x - mu) * inv * w1.x + b1.x;
    o1.y = (a.y - mu) * inv * w1.y + b1.y;
    o1.z = (a.z - mu) * inv * w1.z + b1.z;
    o1.w = (a.w - mu) * inv * w1.w + b1.w;
    o2.x = (bb.x - mu) * inv * w2.x + b2.x;
    o2.y = (bb.y - mu) * inv * w2.y + b2.y;
    o2.z = (bb.z - mu) * inv * w2.z + b2.z;
    o2.w = (bb.w - mu) * inv * w2.w + b2.w;
    o4[(size_t)t * 64 + lane]      = o1;
    o4[(size_t)t * 64 + 32 + lane] = o2;
}

// ---------------------------------------------------------------------------
// tf32 GEMM, 3-stage cp.async pipeline, race-fixed, PDL weight prologue.
// C[M,N] = A[M,K] @ W[N,K]^T.  MODE 0: store | MODE 2: C += acc.
// BM=64*MT, BN=16*NI. Used for in_proj and out_proj.
// ---------------------------------------------------------------------------
template <int MODE, int MT, int NI>
__global__ __launch_bounds__(256)
void gemm_tf32(const float* __restrict__ A, int lda,
               const float* __restrict__ W, int ldw,
               float*       __restrict__ C, int ldc,
               int N, int K, size_t csplit)
{
    const int BM = 64 * MT, BN = 16 * NI, BK = 16, LDS = 20, S = 3;
    __shared__ uint32_t As[S][BM * LDS];
    __shared__ uint32_t Bs[S][BN * LDS];

    A += (size_t)blockIdx.z * K;
    C += (size_t)blockIdx.z * csplit;

    int tid  = threadIdx.x;
    int lane = tid & 31;
    int warp = tid >> 5;
    int m0 = blockIdx.y * BM;
    int n0 = blockIdx.x * BN;
    int wm = (warp >> 1) * 16 * MT;
    int wn = (warp & 1) * 8 * NI;
    int gr = lane >> 2;
    int gc = lane & 3;

    float acc[MT][NI][4];
    #pragma unroll
    for (int mi = 0; mi < MT; mi++)
        #pragma unroll
        for (int ni = 0; ni < NI; ni++)
            #pragma unroll
            for (int e = 0; e < 4; e++) acc[mi][ni][e] = 0.f;

    int lrow = tid >> 2;
    int lcol = (tid & 3) * 4;

    auto issueW = [&](int ti) {
        int buf = ti % S;
        int k0  = ti * BK;
        #pragma unroll
        for (int h = 0; h < NI / 4; h++) {
            int r = lrow + h * 64;
            bool ok = (n0 + r) < N;
            const float* src = ok ? &W[(size_t)(n0 + r) * ldw + k0 + lcol] : W;
            cp_async16_z(&Bs[buf][r * LDS + lcol], src, ok);
        }
    };
    auto issueA = [&](int ti) {
        int buf = ti % S;
        int k0  = ti * BK;
        #pragma unroll
        for (int h = 0; h < MT; h++) {
            int r = lrow + h * 64;
            cp_async16(&As[buf][r * LDS + lcol],
                       &A[(size_t)(m0 + r) * lda + k0 + lcol]);
        }
    };

    int nk = K / BK;
    issueW(0); CP_COMMIT();
    GRID_WAIT();
    issueA(0); CP_COMMIT();
    issueA(1); issueW(1); CP_COMMIT();

    for (int i = 0; i < nk; i++) {
        if (i + 1 < nk) { CP_WAIT1(); } else { CP_WAIT0(); }
        __syncthreads();
        if (i + 2 < nk) { issueA(i + 2); issueW(i + 2); CP_COMMIT(); }
        int buf = i % S;

        #pragma unroll
        for (int ks = 0; ks < BK; ks += 8) {
            uint32_t a[MT][4], b[NI][2];
            #pragma unroll
            for (int mi = 0; mi < MT; mi++) {
                int rb = wm + mi * 16 + gr;
                a[mi][0] = As[buf][rb * LDS + ks + gc];
                a[mi][1] = As[buf][(rb + 8) * LDS + ks + gc];
                a[mi][2] = As[buf][rb * LDS + ks + gc + 4];
                a[mi][3] = As[buf][(rb + 8) * LDS + ks + gc + 4];
            }
            #pragma unroll
            for (int ni = 0; ni < NI; ni++) {
                int rb = wn + ni * 8 + gr;
                b[ni][0] = Bs[buf][rb * LDS + ks + gc];
                b[ni][1] = Bs[buf][rb * LDS + ks + gc + 4];
            }
            #pragma unroll
            for (int mi = 0; mi < MT; mi++)
                #pragma unroll
                for (int ni = 0; ni < NI; ni++)
                    asm volatile(
                        "mma.sync.aligned.m16n8k8.row.col.f32.tf32.tf32.f32 "
                        "{%0,%1,%2,%3}, {%4,%5,%6,%7}, {%8,%9}, {%0,%1,%2,%3};"
                        : "+f"(acc[mi][ni][0]), "+f"(acc[mi][ni][1]),
                          "+f"(acc[mi][ni][2]), "+f"(acc[mi][ni][3])
                        : "r"(a[mi][0]), "r"(a[mi][1]), "r"(a[mi][2]), "r"(a[mi][3]),
                          "r"(b[ni][0]), "r"(b[ni][1]));
        }
    }

    #pragma unroll
    for (int mi = 0; mi < MT; mi++) {
        #pragma unroll
        for (int ni = 0; ni < NI; ni++) {
            int col = n0 + wn + ni * 8 + gc * 2;
            if (col < N) {
                #pragma unroll
                for (int half = 0; half < 2; half++) {
                    int row = m0 + wm + mi * 16 + gr + half * 8;
                    float2 v = make_float2(acc[mi][ni][half * 2],
                                           acc[mi][ni][half * 2 + 1]);
                    float2* cp = (float2*)&C[(size_t)row * ldc + col];
                    if (MODE == 2) {
                        float2 o = *cp;
                        v.x += o.x; v.y += o.y;
                    }
                    *cp = v;
                }
            }
        }
    }
}

// ---------------------------------------------------------------------------
// x_proj dedicated single-shot GEMM: BM=64, whole K-slice (64) in one burst.
// part[z][M,48] = xc[:, z*64:(z+1)*64] @ xpw[:, z*64:..]^T
// Grid (1, NTOK/64, XP_SK). No loop, no per-iter syncs; max per-CTA MLP.
// ---------------------------------------------------------------------------
__global__ __launch_bounds__(256)
void xproj_gemm(const float* __restrict__ A,
                const float* __restrict__ W,
                float* __restrict__ part)
{
    const int LDS = 68;
    __shared__ uint32_t As[64 * LDS];
    __shared__ uint32_t Bs[64 * LDS];

    int tid  = threadIdx.x;
    int lane = tid & 31;
    int warp = tid >> 5;
    int m0 = blockIdx.y * 64;
    int z  = blockIdx.z;
    int wm = (warp >> 1) * 16;
    int wn = (warp & 1) * 32;
    int gr = lane >> 2;
    int gc = lane & 3;

    const float* Ap = A + (size_t)z * KSLICE;
    const float* Wp = W + (size_t)z * KSLICE;
    float*       Cp = part + (size_t)z * NTOK * DBL_COLS;

    int lrow = tid >> 2;          // 0..63

    // PDL prologue: weights before upstream completes
    #pragma unroll
    for (int h = 0; h < 4; h++) {
        int c4 = ((tid & 3) + h * 4) * 4;
        bool ok = lrow < DBL_COLS;
        const float* src = ok ? &Wp[(size_t)lrow * D_INNER + c4] : Wp;
        cp_async16_z(&Bs[lrow * LDS + c4], src, ok);
    }
    CP_COMMIT();
    GRID_WAIT();
    #pragma unroll
    for (int h = 0; h < 4; h++) {
        int c4 = ((tid & 3) + h * 4) * 4;
        cp_async16(&As[lrow * LDS + c4],
                   &Ap[(size_t)(m0 + lrow) * D_INNER + c4]);
    }
    CP_COMMIT();
    CP_WAIT0();
    __syncthreads();

    float acc[4][4];
    #pragma unroll
    for (int ni = 0; ni < 4; ni++)
        #pragma unroll
        for (int e = 0; e < 4; e++) acc[ni][e] = 0.f;

    #pragma unroll
    for (int ks = 0; ks < KSLICE; ks += 8) {
        uint32_t a[4], b[4][2];
        int rb = wm + gr;
        a[0] = As[rb * LDS + ks + gc];
        a[1] = As[(rb + 8) * LDS + ks + gc];
        a[2] = As[rb * LDS + ks + gc + 4];
        a[3] = As[(rb + 8) * LDS + ks + gc + 4];
        #pragma unroll
        for (int ni = 0; ni < 4; ni++) {
            int rbn = wn + ni * 8 + gr;
            b[ni][0] = Bs[rbn * LDS + ks + gc];
            b[ni][1] = Bs[rbn * LDS + ks + gc + 4];
        }
        #pragma unroll
        for (int ni = 0; ni < 4; ni++)
            asm volatile(
                "mma.sync.aligned.m16n8k8.row.col.f32.tf32.tf32.f32 "
                "{%0,%1,%2,%3}, {%4,%5,%6,%7}, {%8,%9}, {%0,%1,%2,%3};"
                : "+f"(acc[ni][0]), "+f"(acc[ni][1]),
                  "+f"(acc[ni][2]), "+f"(acc[ni][3])
                : "r"(a[0]), "r"(a[1]), "r"(a[2]), "r"(a[3]),
                  "r"(b[ni][0]), "r"(b[ni][1]));
    }

    #pragma unroll
    for (int ni = 0; ni < 4; ni++) {
        int col = wn + ni * 8 + gc * 2;
        if (col < DBL_COLS) {
            #pragma unroll
            for (int half = 0; half < 2; half++) {
                int row = m0 + wm + gr + half * 8;
                float2 v = make_float2(acc[ni][half * 2], acc[ni][half * 2 + 1]);
                *(float2*)&Cp[(size_t)row * DBL_COLS + col] = v;
            }
        }
    }
}

// ---------------------------------------------------------------------------
// Reduce x_proj split-K partials (float4) + zero lookback flags
// ---------------------------------------------------------------------------
__global__ void reduce_dbl(const float4* __restrict__ part,
                           float4* __restrict__ dbl,
                           int* __restrict__ flags)
{
    GRID_WAIT();
    int i = blockIdx.x * 256 + threadIdx.x;
    if (i < NFLAGS) flags[i] = 0;
    const int NV = NTOK * DBL_COLS / 4;
    if (i < NV) {
        float4 s = part[i];
        #pragma unroll
        for (int z = 1; z < XP_SK; z++) {
            float4 p = part[(size_t)z * NV + i];
            s.x += p.x; s.y += p.y; s.z += p.z; s.w += p.w;
        }
        dbl[i] = s;
    }
}

// ---------------------------------------------------------------------------
// Depthwise causal conv (D_CONV=4) + SiLU, smem-tiled (read each row once).
// Block = 64 tokens x 64 channels; grid = (NTOK/64)*8 = 512.
// ---------------------------------------------------------------------------
__global__ __launch_bounds__(256)
void conv_silu_kernel(const float* __restrict__ xz,
                      const float* __restrict__ cw,
                      const float* __restrict__ cb,
                      float* __restrict__ xc)
{
    GRID_WAIT();
    const int TT = 64, LDS = 68;
    __shared__ float s_x[(TT + 3) * LDS];

    int tid = threadIdx.x;
    int cg  = blockIdx.x & 7;
    int tb  = blockIdx.x >> 3;
    int t0  = tb * TT;
    int ch0 = cg * 64;
    bool lead = ((t0 & (SEQLEN - 1)) == 0);

    for (int idx = tid; idx < (TT + 3) * 16; idx += 256) {
        int r = idx >> 4, c4 = (idx & 15) * 4;
        float4 v = make_float4(0.f, 0.f, 0.f, 0.f);
        if (!(lead && r < 3))
            v = *(const float4*)&xz[(size_t)(t0 - 3 + r) * (2 * D_INNER) + ch0 + c4];
        *(float4*)&s_x[r * LDS + c4] = v;
    }
    __syncthreads();

    const float4* cw4 = (const float4*)cw;
    for (int idx = tid; idx < TT * 16; idx += 256) {
        int r = idx >> 4, c4 = (idx & 15) * 4;
        int d = ch0 + c4;
        float4 w0 = cw4[d + 0], w1 = cw4[d + 1], w2 = cw4[d + 2], w3 = cw4[d + 3];
        float4 bb = *(const float4*)&cb[d];
        float4 r0 = *(float4*)&s_x[(r + 0) * LDS + c4];
        float4 r1 = *(float4*)&s_x[(r + 1) * LDS + c4];
        float4 r2 = *(float4*)&s_x[(r + 2) * LDS + c4];
        float4 r3 = *(float4*)&s_x[(r + 3) * LDS + c4];
        float4 o;
        o.x = bb.x + r0.x * w0.x + r1.x * w0.y + r2.x * w0.z + r3.x * w0.w;
        o.y = bb.y + r0.y * w1.x + r1.y * w1.y + r2.y * w1.z + r3.y * w1.w;
        o.z = bb.z + r0.z * w2.x + r1.z * w2.y + r2.z * w2.z + r3.z * w2.w;
        o.w = bb.w + r0.w * w3.x + r1.w * w3.y + r2.w * w3.z + r3.w * w3.w;
        o.x = o.x / (1.f + __expf(-o.x));
        o.y = o.y / (1.f + __expf(-o.y));
        o.z = o.z / (1.f + __expf(-o.z));
        o.w = o.w / (1.f + __expf(-o.w));
        *(float4*)&xc[(size_t)(t0 + r) * D_INNER + d] = o;
    }
}

// ---------------------------------------------------------------------------
// Fused selective scan (lookback), float4 staging, batched lookback combine.
// ---------------------------------------------------------------------------
__global__ __launch_bounds__(256)
void scan_fused(const float* __restrict__ dbl,
                const float* __restrict__ xc,
                const float* __restrict__ xz,
                const float* __restrict__ A_log,
                const float* __restrict__ dpw,
                const float* __restrict__ dpb,
                const float* __restrict__ Dp,
                float* __restrict__ cA,
                float* __restrict__ cH,
                int*   __restrict__ flags,
                float* __restrict__ y)
{
    GRID_WAIT();
    __shared__ float s_dt[CLEN * 16];
    __shared__ float s_B [CLEN * 16];
    __shared__ float s_C [CLEN * 16];
    __shared__ float s_xc[CLEN * 16];
    __shared__ float s_dl[CLEN * 16];
    __shared__ float s_pw[16 * 17];
    float* s_y = s_dt;

    int dg = blockIdx.x & 31;
    int c  = (blockIdx.x >> 5) & (NCHUNK - 1);
    int b  = blockIdx.x >> 10;
    int tid = threadIdx.x;
    int n  = tid & 15;
    int dl = tid >> 4;
    int d  = dg * 16 + dl;
    int l0 = c * CLEN;

    const float4* dbl4 = (const float4*)(dbl + ((size_t)b * SEQLEN + l0) * DBL_COLS);
    const float*  xc_p = xc + ((size_t)b * SEQLEN + l0) * D_INNER + dg * 16;

    for (int idx = tid; idx < CLEN * 12; idx += 256) {
        int l = idx / 12, g = idx % 12;
        float4 v = dbl4[l * 12 + g];
        int cc = g * 4;
        float* dst = (cc < 16) ? &s_dt[l * 16 + cc]
                   : (cc < 32) ? &s_B [l * 16 + cc - 16]
                               : &s_C [l * 16 + cc - 32];
        *(float4*)dst = v;
    }
    {
        int l = tid >> 2, g = tid & 3;
        *(float4*)&s_xc[l * 16 + g * 4] =
            *(const float4*)&xc_p[(size_t)l * D_INNER + g * 4];
    }
    {
        int rr = tid >> 4, cc = tid & 15;
        s_pw[rr * 17 + cc] = dpw[(size_t)(dg * 16 + rr) * DT_RANK + cc];
    }
    __syncthreads();

    for (int idx = tid; idx < CLEN * 16; idx += 256) {
        int l = idx >> 4, dd = idx & 15;
        float acc = dpb[dg * 16 + dd];
        #pragma unroll
        for (int r = 0; r < 16; r++)
            acc += s_dt[l * 16 + r] * s_pw[dd * 17 + r];
        s_dl[l * 16 + dd] = (acc > 20.f) ? acc : log1pf(__expf(acc));
    }
    __syncthreads();

    float Adn = -__expf(A_log[d * D_STATE + n]);

    float hloc = 0.f, P = 1.f;
    #pragma unroll 8
    for (int l = 0; l < CLEN; l++) {
        float dv = s_dl[l * 16 + dl];
        float a  = __expf(dv * Adn);
        hloc = a * hloc + (dv * s_xc[l * 16 + dl]) * s_B[l * 16 + n];
        P *= a;
    }

    size_t col_base = (((size_t)b * NCHUNK) * D_INNER + d) * D_STATE + n;
    size_t cstride  = (size_t)D_INNER * D_STATE;
    cA[col_base + (size_t)c * cstride] = P;
    cH[col_base + (size_t)c * cstride] = hloc;
    __threadfence();
    __syncthreads();
    if (tid == 0) {
        int* fp = &flags[(b * NCHUNK + c) * 32 + dg];
        asm volatile("st.release.gpu.b32 [%0], %1;" :: "l"(fp), "r"(1) : "memory");
    }

    float h = 0.f;
    if (c > 0) {
        if (tid < c) {
            const int* fp = &flags[(b * NCHUNK + tid) * 32 + dg];
            int v;
            do {
                asm volatile("ld.acquire.gpu.b32 %0, [%1];" : "=r"(v) : "l"(fp) : "memory");
            } while (v == 0);
        }
        __syncthreads();
        int j = 0;
        for (; j + 4 <= c; j += 4) {
            size_t o0 = col_base + (size_t)(j + 0) * cstride;
            size_t o1 = col_base + (size_t)(j + 1) * cstride;
            size_t o2 = col_base + (size_t)(j + 2) * cstride;
            size_t o3 = col_base + (size_t)(j + 3) * cstride;
            float a0 = cA[o0], h0 = cH[o0];
            float a1 = cA[o1], h1 = cH[o1];
            float a2 = cA[o2], h2 = cH[o2];
            float a3 = cA[o3], h3 = cH[o3];
            h = a0 * h + h0;
            h = a1 * h + h1;
            h = a2 * h + h2;
            h = a3 * h + h3;
        }
        for (; j < c; j++) {
            size_t o = col_base + (size_t)j * cstride;
            h = cA[o] * h + cH[o];
        }
    }

    #pragma unroll 4
    for (int l = 0; l < CLEN; l++) {
        float dv = s_dl[l * 16 + dl];
        h = __expf(dv * Adn) * h + (dv * s_xc[l * 16 + dl]) * s_B[l * 16 + n];
        float p = h * s_C[l * 16 + n];
        p += __shfl_xor_sync(0xffffffffu, p, 8);
        p += __shfl_xor_sync(0xffffffffu, p, 4);
        p += __shfl_xor_sync(0xffffffffu, p, 2);
        p += __shfl_xor_sync(0xffffffffu, p, 1);
        if (n == 0) s_y[l * 16 + dl] = p;
    }
    __syncthreads();

    const float* z_p = xz + ((size_t)b * SEQLEN + l0) * 2 * D_INNER + D_INNER + dg * 16;
    float*       y_p = y  + ((size_t)b * SEQLEN + l0) * D_INNER + dg * 16;
    const float4 Dv = ((const float4*)Dp)[dg * 4 + (tid & 3)];
    {
        int l = tid >> 2, g = tid & 3;
        float4 z4 = *(const float4*)&z_p[(size_t)l * 2 * D_INNER + g * 4];
        float4 yv = *(float4*)&s_y[l * 16 + g * 4];
        float4 xv = *(float4*)&s_xc[l * 16 + g * 4];
        float4 o;
        o.x = (yv.x + xv.x * Dv.x) * (z4.x / (1.f + __expf(-z4.x)));
        o.y = (yv.y + xv.y * Dv.y) * (z4.y / (1.f + __expf(-z4.y)));
        o.z = (yv.z + xv.z * Dv.z) * (z4.z / (1.f + __expf(-z4.z)));
        o.w = (yv.w + xv.w * Dv.w) * (z4.w / (1.f + __expf(-z4.w)));
        *(float4*)&y_p[(size_t)l * D_INNER + g * 4] = o;
    }
}

// ---------------------------------------------------------------------------
// PDL launch helper
// ---------------------------------------------------------------------------
template <typename F, typename... Args>
static void launch_pdl(F* kern, dim3 grid, dim3 block, Args... args)
{
    cudaLaunchConfig_t cfg = {};
    cfg.gridDim = grid;
    cfg.blockDim = block;
    cfg.dynamicSmemBytes = 0;
    cudaLaunchAttribute attr[1];
    attr[0].id = cudaLaunchAttributeProgrammaticStreamSerialization;
    attr[0].val.programmaticStreamSerializationAllowed = 1;
    cfg.attrs = attr;
    cfg.numAttrs = 1;
    cudaLaunchKernelEx(&cfg, kern, args...);
}

// ---------------------------------------------------------------------------
// Launcher
// ---------------------------------------------------------------------------
extern "C" void kernel_launch(void* const* d_in, const int* in_sizes, int n_in,
                              void* d_out, int out_size)
{
    const float* x_in = (const float*)d_in[0];
    const float* ln_w = (const float*)d_in[1];
    const float* ln_b = (const float*)d_in[2];
    const float* ipw  = (const float*)d_in[3];
    const float* cw   = (const float*)d_in[4];
    const float* cb   = (const float*)d_in[5];
    const float* xpw  = (const float*)d_in[6];
    const float* dpw  = (const float*)d_in[7];
    const float* dpb  = (const float*)d_in[8];
    const float* alog = (const float*)d_in[9];
    const float* dpar = (const float*)d_in[10];
    const float* opw  = (const float*)d_in[11];
    float* xbuf = (float*)d_out;

    float *p_h, *p_xz, *p_xc, *p_dbl, *p_part, *p_y, *p_cA, *p_cH;
    int* p_flag;
    cudaGetSymbolAddress((void**)&p_h,    g_h);
    cudaGetSymbolAddress((void**)&p_xz,   g_xz);
    cudaGetSymbolAddress((void**)&p_xc,   g_xc);
    cudaGetSymbolAddress((void**)&p_dbl,  g_dbl);
    cudaGetSymbolAddress((void**)&p_part, g_part);
    cudaGetSymbolAddress((void**)&p_y,    g_y);
    cudaGetSymbolAddress((void**)&p_cA,   g_cA);
    cudaGetSymbolAddress((void**)&p_cH,   g_cH);
    cudaGetSymbolAddress((void**)&p_flag, g_flag);

    cudaMemcpyAsync(xbuf, x_in, (size_t)NTOK * D_MODEL * sizeof(float),
                    cudaMemcpyDeviceToDevice);

    const int SCAN_BLOCKS = BATCH * NCHUNK * 32;
    const int CONV_BLOCKS = (NTOK / 64) * 8;

    for (int layer = 0; layer < DEPTH; layer++) {
        const float* l_lnw  = ln_w + layer * D_MODEL;
        const float* l_lnb  = ln_b + layer * D_MODEL;
        const float* l_ipw  = ipw  + (size_t)layer * 2 * D_INNER * D_MODEL;
        const float* l_cw   = cw   + (size_t)layer * D_INNER * D_CONV;
        const float* l_cb   = cb   + (size_t)layer * D_INNER;
        const float* l_xpw  = xpw  + (size_t)layer * DBL_COLS * D_INNER;
        const float* l_dpw  = dpw  + (size_t)layer * D_INNER * DT_RANK;
        const float* l_dpb  = dpb  + (size_t)layer * D_INNER;
        const float* l_alog = alog + (size_t)layer * D_INNER * D_STATE;
        const float* l_dpar = dpar + (size_t)layer * D_INNER;
        const float* l_opw  = opw  + (size_t)layer * D_MODEL * D_INNER;

        // 1. LayerNorm (warp per token)
        launch_pdl(ln_kernel, dim3(NTOK / 8), dim3(256),
                   (const float*)xbuf, l_lnw, l_lnb, p_h);

        // 2. in_proj: BM=128, BN=64 -> 512 CTAs
        launch_pdl(gemm_tf32<0, 2, 4>, dim3(16, NTOK / 128, 1), dim3(256),
                   (const float*)p_h, D_MODEL, l_ipw, D_MODEL,
                   p_xz, 2 * D_INNER, 2 * D_INNER, D_MODEL, (size_t)0);

        // 3. conv + silu (smem-tiled, read-once)
        launch_pdl(conv_silu_kernel, dim3(CONV_BLOCKS), dim3(256),
                   (const float*)p_xz, l_cw, l_cb, p_xc);

        // 4. x_proj single-shot split-K=8 -> 512 CTAs, then reduce (+ flags)
        launch_pdl(xproj_gemm, dim3(1, NTOK / 64, XP_SK), dim3(256),
                   (const float*)p_xc, l_xpw, p_part);
        launch_pdl(reduce_dbl, dim3((NTOK * DBL_COLS / 4 + 255) / 256), dim3(256),
                   (const float4*)p_part, (float4*)p_dbl, p_flag);

        // 5. fused scan
        launch_pdl(scan_fused, dim3(SCAN_BLOCKS), dim3(256),
                   (const float*)p_dbl, (const float*)p_xc,
                   (const float*)p_xz, l_alog, l_dpw, l_dpb, l_dpar,
                   p_cA, p_cH, p_flag, p_y);

        // 6. out_proj + residual: BM=128 -> 128 CTAs
        launch_pdl(gemm_tf32<2, 2, 4>, dim3(4, NTOK / 128, 1), dim3(256),
                   (const float*)p_y, D_INNER, l_opw, D_INNER,
                   xbuf, D_MODEL, D_MODEL, D_INNER, (size_t)0);
    }
}